// round 1
// baseline (speedup 1.0000x reference)
#include <cuda_runtime.h>
#include <math.h>

#define Nq   20000
#define Mv   80000
#define KK   48
#define Cdim 64
#define FFd  256
#define Hh   4
#define HD   16
#define OUTd 64
#define PAD  65

// ---- scratch (no allocations allowed) ----
__device__ float  g_x[Nq * Cdim];     // pre-BN1 activations
__device__ float  g_z[Nq * OUTd];     // pre-BN2 activations
__device__ double g_sum1[Cdim], g_sq1[Cdim];
__device__ double g_sum2[OUTd], g_sq2[OUTd];
__device__ float  g_mu1[Cdim], g_rs1[Cdim];
__device__ float  g_mu2[OUTd], g_rs2[OUTd];

__global__ void zero_stats() {
    int t = threadIdx.x;
    if (t < Cdim) { g_sum1[t] = 0.0; g_sq1[t] = 0.0; }
    if (t < OUTd) { g_sum2[t] = 0.0; g_sq2[t] = 0.0; }
}

__device__ __forceinline__ float warp_red(float v) {
    v += __shfl_down_sync(0xffffffffu, v, 16);
    v += __shfl_down_sync(0xffffffffu, v, 8);
    v += __shfl_down_sync(0xffffffffu, v, 4);
    v += __shfl_down_sync(0xffffffffu, v, 2);
    v += __shfl_down_sync(0xffffffffu, v, 1);
    return v;
}

// ===================== main attention + FFN kernel: one block per query =====================
__global__ __launch_bounds__(256) void attn_kernel(
    const float* __restrict__ vf,     const float* __restrict__ vc,
    const float* __restrict__ qc,     const int*   __restrict__ kidx,
    const float* __restrict__ q_w,    const float* __restrict__ q_b,
    const float* __restrict__ kpos_w, const float* __restrict__ kpos_b,
    const float* __restrict__ in_w,   const float* __restrict__ in_b,
    const float* __restrict__ out_w,  const float* __restrict__ out_b,
    const float* __restrict__ lin1_w, const float* __restrict__ lin1_b,
    const float* __restrict__ lin2_w, const float* __restrict__ lin2_b)
{
    const int n    = blockIdx.x;
    const int tid  = threadIdx.x;
    const int lane = tid & 31;
    const int warp = tid >> 5;

    __shared__ float s_kf[KK * PAD];   // gathered + positional key features
    __shared__ float s_kp[KK * PAD];   // K projection
    __shared__ float s_vp[KK * PAD];   // V projection
    __shared__ float s_qfeat[Cdim];
    __shared__ float s_q[Cdim];
    __shared__ float s_sc[Hh * KK];
    __shared__ float s_ctx[Cdim];
    __shared__ float s_att[Cdim];
    __shared__ float s_hid[FFd];
    __shared__ int   s_idx[KK];

    const float qc0 = qc[n * 3 + 0], qc1 = qc[n * 3 + 1], qc2 = qc[n * 3 + 2];

    if (tid < KK) s_idx[tid] = kidx[n * KK + tid];
    if (tid >= 64 && tid < 128) {
        int c = tid - 64;
        float a = q_b[c] + q_w[c * 3] * qc0 + q_w[c * 3 + 1] * qc1 + q_w[c * 3 + 2] * qc2;
        s_qfeat[c] = fmaxf(a, 0.f);
    }
    __syncthreads();

    // ---- gather key features + positional term (fused) ----
    for (int i = tid; i < KK * Cdim; i += 256) {
        int kk = i >> 6, c = i & 63;
        int idx = s_idx[kk]; if (idx < 0) idx = 0;
        float f  = vf[idx * Cdim + c];
        float r0 = vc[idx * 3 + 0] - qc0;
        float r1 = vc[idx * 3 + 1] - qc1;
        float r2 = vc[idx * 3 + 2] - qc2;
        float p  = kpos_b[c] + kpos_w[c * 3] * r0 + kpos_w[c * 3 + 1] * r1 + kpos_w[c * 3 + 2] * r2;
        s_kf[kk * PAD + c] = f + fmaxf(p, 0.f);
    }
    // ---- q = (Wq @ qfeat + bq) / sqrt(hd), warp-per-output (coalesced weights) ----
    for (int c = warp; c < Cdim; c += 8) {
        float acc = in_w[c * Cdim + lane]      * s_qfeat[lane]
                  + in_w[c * Cdim + lane + 32] * s_qfeat[lane + 32];
        acc = warp_red(acc);
        if (lane == 0) s_q[c] = (acc + in_b[c]) * 0.25f;
    }
    __syncthreads();

    // ---- K/V projections: i = c*48+kk ordering -> weight loads warp-uniform,
    //      smem keyfeat reads stride-65 conflict-free ----
    for (int i = tid; i < KK * Cdim; i += 256) {
        int c  = i / KK;
        int kk = i - c * KK;
        float aK = in_b[64 + c], aV = in_b[128 + c];
        const float* wk = in_w + (64 + c)  * Cdim;
        const float* wv = in_w + (128 + c) * Cdim;
        const float* kf = s_kf + kk * PAD;
        #pragma unroll
        for (int j = 0; j < Cdim; ++j) {
            float f = kf[j];
            aK = fmaf(wk[j], f, aK);
            aV = fmaf(wv[j], f, aV);
        }
        s_kp[kk * PAD + c] = aK;
        s_vp[kk * PAD + c] = aV;
    }
    __syncthreads();

    // ---- scores (h, kk) ----
    if (tid < Hh * KK) {
        int h = tid / KK, kk = tid - h * KK;
        const float* qh = s_q  + h * HD;
        const float* kp = s_kp + kk * PAD + h * HD;
        float s = 0.f;
        #pragma unroll
        for (int d = 0; d < HD; ++d) s = fmaf(qh[d], kp[d], s);
        s_sc[h * KK + kk] = (s_idx[kk] < 0) ? -1e30f : s;
    }
    __syncthreads();

    // ---- softmax per head ----
    if (tid < Hh) {
        float* sc = s_sc + tid * KK;
        float mx = -1e30f;
        for (int kk = 0; kk < KK; ++kk) mx = fmaxf(mx, sc[kk]);
        float sum = 0.f;
        for (int kk = 0; kk < KK; ++kk) { float e = __expf(sc[kk] - mx); sc[kk] = e; sum += e; }
        float inv = 1.f / sum;
        for (int kk = 0; kk < KK; ++kk) sc[kk] *= inv;
    }
    __syncthreads();

    // ---- ctx = attn @ V ----
    if (tid < Cdim) {
        int h = tid >> 4;
        const float* a = s_sc + h * KK;
        float acc = 0.f;
        #pragma unroll
        for (int kk = 0; kk < KK; ++kk) acc = fmaf(a[kk], s_vp[kk * PAD + tid], acc);
        s_ctx[tid] = acc;
    }
    __syncthreads();

    // ---- att = out_w @ ctx + out_b ----
    for (int c = warp; c < Cdim; c += 8) {
        float acc = out_w[c * Cdim + lane]      * s_ctx[lane]
                  + out_w[c * Cdim + lane + 32] * s_ctx[lane + 32];
        acc = warp_red(acc);
        if (lane == 0) s_att[c] = acc + out_b[c];
    }
    __syncthreads();

    // ---- hidden = relu(lin1 @ att + b1) ----
    for (int f = warp; f < FFd; f += 8) {
        float acc = lin1_w[f * Cdim + lane]      * s_att[lane]
                  + lin1_w[f * Cdim + lane + 32] * s_att[lane + 32];
        acc = warp_red(acc);
        if (lane == 0) s_hid[f] = fmaxf(acc + lin1_b[f], 0.f);
    }
    __syncthreads();

    // ---- x = att + lin2 @ hidden + b2 -> g_x ----
    for (int c = warp; c < Cdim; c += 8) {
        float acc = 0.f;
        #pragma unroll
        for (int j = lane; j < FFd; j += 32) acc = fmaf(lin2_w[c * FFd + j], s_hid[j], acc);
        acc = warp_red(acc);
        if (lane == 0) g_x[n * Cdim + c] = s_att[c] + acc + lin2_b[c];
    }
}

// ===================== column stats (sum, sumsq) over N rows, 64 cols =====================
__global__ void stats1_kernel() {
    __shared__ double s_s[4][64], s_q2[4][64];
    int tid = threadIdx.x;
    int col = tid & 63, sub = tid >> 6;
    double a = 0, b = 0;
    for (int r = blockIdx.x * 4 + sub; r < Nq; r += gridDim.x * 4) {
        float v = g_x[r * 64 + col];
        a += v; b += (double)v * v;
    }
    s_s[sub][col] = a; s_q2[sub][col] = b;
    __syncthreads();
    if (tid < 64) {
        atomicAdd(&g_sum1[tid], s_s[0][tid] + s_s[1][tid] + s_s[2][tid] + s_s[3][tid]);
        atomicAdd(&g_sq1[tid],  s_q2[0][tid] + s_q2[1][tid] + s_q2[2][tid] + s_q2[3][tid]);
    }
}

__global__ void stats2_kernel() {
    __shared__ double s_s[4][64], s_q2[4][64];
    int tid = threadIdx.x;
    int col = tid & 63, sub = tid >> 6;
    double a = 0, b = 0;
    for (int r = blockIdx.x * 4 + sub; r < Nq; r += gridDim.x * 4) {
        float v = g_z[r * 64 + col];
        a += v; b += (double)v * v;
    }
    s_s[sub][col] = a; s_q2[sub][col] = b;
    __syncthreads();
    if (tid < 64) {
        atomicAdd(&g_sum2[tid], s_s[0][tid] + s_s[1][tid] + s_s[2][tid] + s_s[3][tid]);
        atomicAdd(&g_sq2[tid],  s_q2[0][tid] + s_q2[1][tid] + s_q2[2][tid] + s_q2[3][tid]);
    }
}

__global__ void finalize1_kernel() {
    int t = threadIdx.x;
    if (t < Cdim) {
        double m = g_sum1[t] / (double)Nq;
        double v = g_sq1[t] / (double)Nq - m * m;
        if (v < 0) v = 0;
        g_mu1[t] = (float)m;
        g_rs1[t] = (float)(1.0 / sqrt(v + 1e-5));
    }
}

__global__ void finalize2_kernel() {
    int t = threadIdx.x;
    if (t < OUTd) {
        double m = g_sum2[t] / (double)Nq;
        double v = g_sq2[t] / (double)Nq - m * m;
        if (v < 0) v = 0;
        g_mu2[t] = (float)m;
        g_rs2[t] = (float)(1.0 / sqrt(v + 1e-5));
    }
}

// ===================== BN1 + output linear: z = outl_w @ BN1(x) + outl_b =====================
__global__ __launch_bounds__(256) void proj_kernel(
    const float* __restrict__ outl_w, const float* __restrict__ outl_b,
    const float* __restrict__ norm_g, const float* __restrict__ norm_b)
{
    __shared__ float s_wt[64 * PAD];   // transposed weights: s_wt[c*PAD + o] = w[o*64 + c]
    __shared__ float s_x[16 * 64];
    int tid = threadIdx.x;

    for (int i = tid; i < 64 * 64; i += 256) {
        int o = i >> 6, c = i & 63;
        s_wt[c * PAD + o] = outl_w[i];
    }
    int base = blockIdx.x * 16 * 64;
    for (int i = tid; i < 16 * 64; i += 256) {
        int c = i & 63;
        s_x[i] = (g_x[base + i] - g_mu1[c]) * g_rs1[c] * norm_g[c] + norm_b[c];
    }
    __syncthreads();

    int o = tid & 63;
    for (int rr = 0; rr < 4; ++rr) {
        int r = (tid >> 6) + rr * 4;
        const float* x = s_x + r * 64;
        float acc = outl_b[o];
        #pragma unroll
        for (int c = 0; c < 64; ++c) acc = fmaf(s_wt[c * PAD + o], x[c], acc);
        g_z[base + r * 64 + o] = acc;
    }
}

// ===================== final BN2 + relu =====================
__global__ void final_kernel(float* __restrict__ out,
                             const float* __restrict__ obn_g,
                             const float* __restrict__ obn_b)
{
    int i = blockIdx.x * 256 + threadIdx.x;
    if (i < Nq * OUTd) {
        int o = i & 63;
        float v = (g_z[i] - g_mu2[o]) * g_rs2[o] * obn_g[o] + obn_b[o];
        out[i] = fmaxf(v, 0.f);
    }
}

extern "C" void kernel_launch(void* const* d_in, const int* in_sizes, int n_in,
                              void* d_out, int out_size) {
    const float* vf     = (const float*)d_in[0];
    const float* vc     = (const float*)d_in[1];
    const float* qcoord = (const float*)d_in[2];
    const int*   kidx   = (const int*)  d_in[3];
    const float* q_w    = (const float*)d_in[4];
    const float* q_b    = (const float*)d_in[5];
    const float* kpos_w = (const float*)d_in[6];
    const float* kpos_b = (const float*)d_in[7];
    const float* in_w   = (const float*)d_in[8];
    const float* in_b   = (const float*)d_in[9];
    const float* out_w  = (const float*)d_in[10];
    const float* out_b  = (const float*)d_in[11];
    const float* lin1_w = (const float*)d_in[12];
    const float* lin1_b = (const float*)d_in[13];
    const float* lin2_w = (const float*)d_in[14];
    const float* lin2_b = (const float*)d_in[15];
    const float* norm_g = (const float*)d_in[16];
    const float* norm_b = (const float*)d_in[17];
    const float* outl_w = (const float*)d_in[18];
    const float* outl_b = (const float*)d_in[19];
    const float* obn_g  = (const float*)d_in[20];
    const float* obn_b  = (const float*)d_in[21];
    float* out = (float*)d_out;

    zero_stats<<<1, 64>>>();
    attn_kernel<<<Nq, 256>>>(vf, vc, qcoord, kidx, q_w, q_b, kpos_w, kpos_b,
                             in_w, in_b, out_w, out_b, lin1_w, lin1_b, lin2_w, lin2_b);
    stats1_kernel<<<256, 256>>>();
    finalize1_kernel<<<1, 64>>>();
    proj_kernel<<<Nq / 16, 256>>>(outl_w, outl_b, norm_g, norm_b);
    stats2_kernel<<<256, 256>>>();
    finalize2_kernel<<<1, 64>>>();
    final_kernel<<<(Nq * OUTd + 255) / 256, 256>>>(out, obn_g, obn_b);
}

// round 3
// speedup vs baseline: 1.7595x; 1.7595x over previous
#include <cuda_runtime.h>
#include <math.h>

#define Nq   20000
#define KK   48
#define Cdim 64
#define FFd  256
#define Hh   4
#define HD   16
#define OUTd 64
#define PAD  65

typedef unsigned long long ull;

// ---- scratch (no allocations allowed) ----
__device__ float  g_att[Nq * Cdim];   // attention output (pre-FFN)
__device__ float  g_x[Nq * Cdim];     // pre-BN1 activations
__device__ float  g_z[Nq * OUTd];     // pre-BN2 activations
__device__ double g_sum1[Cdim], g_sq1[Cdim];
__device__ double g_sum2[OUTd], g_sq2[OUTd];
__device__ float  g_mu1[Cdim], g_rs1[Cdim];
__device__ float  g_mu2[OUTd], g_rs2[OUTd];

// ---- f32x2 packed math (Blackwell FFMA2 path) ----
__device__ __forceinline__ ull pk2(float lo, float hi) {
    ull r; asm("mov.b64 %0, {%1, %2};" : "=l"(r) : "f"(lo), "f"(hi)); return r;
}
__device__ __forceinline__ void upk2(ull v, float& lo, float& hi) {
    asm("mov.b64 {%0, %1}, %2;" : "=f"(lo), "=f"(hi) : "l"(v));
}
__device__ __forceinline__ ull fma2(ull a, ull b, ull c) {
    ull d; asm("fma.rn.f32x2 %0, %1, %2, %3;" : "=l"(d) : "l"(a), "l"(b), "l"(c)); return d;
}
__device__ __forceinline__ ull add2(ull a, ull b) {
    ull d; asm("add.rn.f32x2 %0, %1, %2;" : "=l"(d) : "l"(a), "l"(b)); return d;
}

__global__ void zero_stats() {
    int t = threadIdx.x;
    if (t < Cdim) { g_sum1[t] = 0.0; g_sq1[t] = 0.0; }
    if (t < OUTd) { g_sum2[t] = 0.0; g_sq2[t] = 0.0; }
}

__device__ __forceinline__ float warp_red(float v) {
    v += __shfl_down_sync(0xffffffffu, v, 16);
    v += __shfl_down_sync(0xffffffffu, v, 8);
    v += __shfl_down_sync(0xffffffffu, v, 4);
    v += __shfl_down_sync(0xffffffffu, v, 2);
    v += __shfl_down_sync(0xffffffffu, v, 1);
    return v;
}

// ================= attention kernel: one block per query =================
#define SMEM_ATTN (32768 + 24960 + 12480 + 12480 + 1536 + 192)

__global__ __launch_bounds__(256) void attn_kernel(
    const float* __restrict__ vf,     const float* __restrict__ vc,
    const float* __restrict__ qc,     const int*   __restrict__ kidx,
    const float* __restrict__ q_w,    const float* __restrict__ q_b,
    const float* __restrict__ kpos_w, const float* __restrict__ kpos_b,
    const float* __restrict__ in_w,   const float* __restrict__ in_b,
    const float* __restrict__ out_w,  const float* __restrict__ out_b)
{
    extern __shared__ char smem[];
    ull*   s_wkvT = (ull*)smem;               // 4096 ull
    ull*   s_kf2  = s_wkvT + 4096;            // 3120 ull
    float* s_kp   = (float*)(s_kf2 + 3120);   // 3120 f
    float* s_vp   = s_kp + 3120;              // 3120 f
    float* s_qf   = s_vp + 3120;              // 64
    float* s_q    = s_qf + 64;                // 64
    float* s_sc   = s_q + 64;                 // 192
    float* s_ctx  = s_sc + 192;               // 64
    int*   s_idx  = (int*)(s_ctx + 64);       // 48

    const int n    = blockIdx.x;
    const int tid  = threadIdx.x;
    const int lane = tid & 31;
    const int warp = tid >> 5;

    const float qc0 = qc[n * 3 + 0], qc1 = qc[n * 3 + 1], qc2 = qc[n * 3 + 2];

    // stage interleaved (Wk,Wv) transposed: s_wkvT[j*64 + c]
    for (int idx = tid; idx < 1024; idx += 256) {
        int j4 = idx & 15, c = idx >> 4;
        float4 k4 = *(const float4*)(in_w + (64  + c) * 64 + j4 * 4);
        float4 v4 = *(const float4*)(in_w + (128 + c) * 64 + j4 * 4);
        s_wkvT[(j4*4+0)*64 + c] = pk2(k4.x, v4.x);
        s_wkvT[(j4*4+1)*64 + c] = pk2(k4.y, v4.y);
        s_wkvT[(j4*4+2)*64 + c] = pk2(k4.z, v4.z);
        s_wkvT[(j4*4+3)*64 + c] = pk2(k4.w, v4.w);
    }
    if (tid < KK) s_idx[tid] = kidx[n * KK + tid];
    if (tid >= 64 && tid < 128) {
        int c = tid - 64;
        float a = q_b[c] + q_w[c * 3] * qc0 + q_w[c * 3 + 1] * qc1 + q_w[c * 3 + 2] * qc2;
        s_qf[c] = fmaxf(a, 0.f);
    }
    __syncthreads();

    // gather key features + positional term (duplicated pack)
    for (int i = tid; i < KK * Cdim; i += 256) {
        int kk = i >> 6, c = i & 63;
        int idx = s_idx[kk]; if (idx < 0) idx = 0;
        float f  = vf[idx * Cdim + c];
        float r0 = vc[idx * 3 + 0] - qc0;
        float r1 = vc[idx * 3 + 1] - qc1;
        float r2 = vc[idx * 3 + 2] - qc2;
        float p  = kpos_b[c] + kpos_w[c * 3] * r0 + kpos_w[c * 3 + 1] * r1 + kpos_w[c * 3 + 2] * r2;
        float val = f + fmaxf(p, 0.f);
        s_kf2[kk * PAD + c] = pk2(val, val);
    }
    // q projection (warp per output)
    for (int c = warp; c < Cdim; c += 8) {
        float acc = in_w[c * Cdim + lane]      * s_qf[lane]
                  + in_w[c * Cdim + lane + 32] * s_qf[lane + 32];
        acc = warp_red(acc);
        if (lane == 0) s_q[c] = (acc + in_b[c]) * 0.25f;
    }
    __syncthreads();

    // ---- K/V projection: register-tiled 3kk x 4c, packed (K,V) FFMA2 ----
    {
        const int kkg = tid & 15, cg = tid >> 4;
        const int kk0 = kkg * 3, c0 = cg * 4;
        ull acc0[4], acc1[4], acc2[4];
        #pragma unroll
        for (int u = 0; u < 4; ++u) {
            ull b = pk2(in_b[64 + c0 + u], in_b[128 + c0 + u]);
            acc0[u] = b; acc1[u] = b; acc2[u] = b;
        }
        const ull* kfp = s_kf2 + kk0 * PAD;
        #pragma unroll 8
        for (int j = 0; j < 64; ++j) {
            ull f0 = kfp[j];
            ull f1 = kfp[PAD + j];
            ull f2 = kfp[2 * PAD + j];
            ulonglong2 wA = *(const ulonglong2*)(s_wkvT + j * 64 + c0);
            ulonglong2 wB = *(const ulonglong2*)(s_wkvT + j * 64 + c0 + 2);
            acc0[0] = fma2(wA.x, f0, acc0[0]);
            acc0[1] = fma2(wA.y, f0, acc0[1]);
            acc0[2] = fma2(wB.x, f0, acc0[2]);
            acc0[3] = fma2(wB.y, f0, acc0[3]);
            acc1[0] = fma2(wA.x, f1, acc1[0]);
            acc1[1] = fma2(wA.y, f1, acc1[1]);
            acc1[2] = fma2(wB.x, f1, acc1[2]);
            acc1[3] = fma2(wB.y, f1, acc1[3]);
            acc2[0] = fma2(wA.x, f2, acc2[0]);
            acc2[1] = fma2(wA.y, f2, acc2[1]);
            acc2[2] = fma2(wB.x, f2, acc2[2]);
            acc2[3] = fma2(wB.y, f2, acc2[3]);
        }
        #pragma unroll
        for (int u = 0; u < 4; ++u) {
            float a, b;
            upk2(acc0[u], a, b); s_kp[kk0 * PAD + c0 + u] = a; s_vp[kk0 * PAD + c0 + u] = b;
            upk2(acc1[u], a, b); s_kp[(kk0+1) * PAD + c0 + u] = a; s_vp[(kk0+1) * PAD + c0 + u] = b;
            upk2(acc2[u], a, b); s_kp[(kk0+2) * PAD + c0 + u] = a; s_vp[(kk0+2) * PAD + c0 + u] = b;
        }
    }
    __syncthreads();

    // ---- scores ----
    if (tid < Hh * KK) {
        int h = tid / KK, kk = tid - h * KK;
        const float* qh = s_q  + h * HD;
        const float* kp = s_kp + kk * PAD + h * HD;
        float s = 0.f;
        #pragma unroll
        for (int d = 0; d < HD; ++d) s = fmaf(qh[d], kp[d], s);
        s_sc[h * KK + kk] = (s_idx[kk] < 0) ? -1e30f : s;
    }
    __syncthreads();

    // ---- softmax: one warp per head ----
    if (warp < Hh) {
        float v0 = s_sc[warp * KK + lane];
        float v1 = (lane < 16) ? s_sc[warp * KK + 32 + lane] : -1e30f;
        float m = fmaxf(v0, v1);
        #pragma unroll
        for (int o = 16; o > 0; o >>= 1) m = fmaxf(m, __shfl_xor_sync(0xffffffffu, m, o));
        float e0 = __expf(v0 - m);
        float e1 = (lane < 16) ? __expf(v1 - m) : 0.f;
        float s = e0 + e1;
        #pragma unroll
        for (int o = 16; o > 0; o >>= 1) s += __shfl_xor_sync(0xffffffffu, s, o);
        float inv = 1.f / s;
        s_sc[warp * KK + lane] = e0 * inv;
        if (lane < 16) s_sc[warp * KK + 32 + lane] = e1 * inv;
    }
    __syncthreads();

    // ---- ctx = attn @ V ----
    if (tid < Cdim) {
        int h = tid >> 4;
        const float* a = s_sc + h * KK;
        float acc = 0.f;
        #pragma unroll
        for (int kk = 0; kk < KK; ++kk) acc = fmaf(a[kk], s_vp[kk * PAD + tid], acc);
        s_ctx[tid] = acc;
    }
    __syncthreads();

    // ---- att = out_w @ ctx + out_b -> g_att ----
    for (int c = warp; c < Cdim; c += 8) {
        float acc = out_w[c * Cdim + lane]      * s_ctx[lane]
                  + out_w[c * Cdim + lane + 32] * s_ctx[lane + 32];
        acc = warp_red(acc);
        if (lane == 0) g_att[n * Cdim + c] = acc + out_b[c];
    }
}

// ================= FFN kernel: x = att + lin2(relu(lin1 att)) =================
#define FRPB 136
#define W1PAD 258
#define W2PAD 66
#define SMEM_FFN ((128 + 512 + 256) * 8 + (64 * W1PAD + 256 * W2PAD) * 4)

__global__ __launch_bounds__(256) void ffn_kernel(
    const float* __restrict__ lin1_w, const float* __restrict__ lin1_b,
    const float* __restrict__ lin2_w, const float* __restrict__ lin2_b)
{
    extern __shared__ char smem[];
    ull*   s_att2 = (ull*)smem;            // [2][64]
    ull*   s_h2   = s_att2 + 128;          // [2][256]
    ull*   s_red  = s_h2 + 512;            // [256]
    float* s_w1t  = (float*)(s_red + 256); // [64][258]
    float* s_w2t  = s_w1t + 64 * W1PAD;    // [256][66]

    const int tid = threadIdx.x;

    for (int i = tid; i < FFd * Cdim; i += 256) {
        int f = i >> 6, j = i & 63;
        s_w1t[j * W1PAD + f] = lin1_w[i];
    }
    for (int i = tid; i < Cdim * FFd; i += 256) {
        int c = i >> 8, j = i & 255;
        s_w2t[j * W2PAD + c] = lin2_w[i];
    }
    const int p_ = tid & 127;
    const ull bias1 = pk2(lin1_b[2 * p_], lin1_b[2 * p_ + 1]);

    const int r0 = blockIdx.x * FRPB;
    for (int it = 0; it < FRPB / 2; ++it) {
        const int row0 = r0 + it * 2;
        __syncthreads();
        if (tid < 128) {
            int r = tid >> 6, j = tid & 63;
            int row = row0 + r;
            float v = (row < Nq) ? g_att[row * 64 + j] : 0.f;
            s_att2[r * 64 + j] = pk2(v, v);
        }
        __syncthreads();
        // hidden = relu(W1 att + b1), pair over f
        {
            int r = tid >> 7, p = tid & 127;
            ull acc = bias1;
            #pragma unroll 8
            for (int j = 0; j < 64; ++j)
                acc = fma2(((const ull*)(s_w1t + j * W1PAD))[p], s_att2[r * 64 + j], acc);
            float h0, h1; upk2(acc, h0, h1);
            h0 = fmaxf(h0, 0.f); h1 = fmaxf(h1, 0.f);
            s_h2[r * 256 + 2 * p]     = pk2(h0, h0);
            s_h2[r * 256 + 2 * p + 1] = pk2(h1, h1);
        }
        __syncthreads();
        // lin2 partials: (row, jseg, cpair)
        {
            int r = tid >> 7, s = (tid >> 5) & 3, cp = tid & 31;
            ull acc = 0;
            int j0 = s * 64;
            #pragma unroll 8
            for (int j = 0; j < 64; ++j)
                acc = fma2(((const ull*)(s_w2t + (j0 + j) * W2PAD))[cp],
                           s_h2[r * 256 + j0 + j], acc);
            s_red[tid] = acc;
        }
        __syncthreads();
        if (tid < 64) {
            int r = tid >> 5, cp = tid & 31;
            ull a = add2(add2(s_red[r * 128 + cp],      s_red[r * 128 + 32 + cp]),
                         add2(s_red[r * 128 + 64 + cp], s_red[r * 128 + 96 + cp]));
            float x0, x1; upk2(a, x0, x1);
            float a0, t; upk2(s_att2[r * 64 + 2 * cp], a0, t);
            float a1;    upk2(s_att2[r * 64 + 2 * cp + 1], a1, t);
            int row = row0 + r;
            if (row < Nq) {
                float2 o;
                o.x = a0 + x0 + lin2_b[2 * cp];
                o.y = a1 + x1 + lin2_b[2 * cp + 1];
                *(float2*)(g_x + row * 64 + 2 * cp) = o;
            }
        }
    }
}

// ===================== column stats over N rows =====================
__global__ void stats1_kernel() {
    __shared__ double s_s[4][64], s_q2[4][64];
    int tid = threadIdx.x;
    int col = tid & 63, sub = tid >> 6;
    double a = 0, b = 0;
    for (int r = blockIdx.x * 4 + sub; r < Nq; r += gridDim.x * 4) {
        float v = g_x[r * 64 + col];
        a += v; b += (double)v * v;
    }
    s_s[sub][col] = a; s_q2[sub][col] = b;
    __syncthreads();
    if (tid < 64) {
        atomicAdd(&g_sum1[tid], s_s[0][tid] + s_s[1][tid] + s_s[2][tid] + s_s[3][tid]);
        atomicAdd(&g_sq1[tid],  s_q2[0][tid] + s_q2[1][tid] + s_q2[2][tid] + s_q2[3][tid]);
    }
}

__global__ void stats2_kernel() {
    __shared__ double s_s[4][64], s_q2[4][64];
    int tid = threadIdx.x;
    int col = tid & 63, sub = tid >> 6;
    double a = 0, b = 0;
    for (int r = blockIdx.x * 4 + sub; r < Nq; r += gridDim.x * 4) {
        float v = g_z[r * 64 + col];
        a += v; b += (double)v * v;
    }
    s_s[sub][col] = a; s_q2[sub][col] = b;
    __syncthreads();
    if (tid < 64) {
        atomicAdd(&g_sum2[tid], s_s[0][tid] + s_s[1][tid] + s_s[2][tid] + s_s[3][tid]);
        atomicAdd(&g_sq2[tid],  s_q2[0][tid] + s_q2[1][tid] + s_q2[2][tid] + s_q2[3][tid]);
    }
}

__global__ void finalize1_kernel() {
    int t = threadIdx.x;
    if (t < Cdim) {
        double m = g_sum1[t] / (double)Nq;
        double v = g_sq1[t] / (double)Nq - m * m;
        if (v < 0) v = 0;
        g_mu1[t] = (float)m;
        g_rs1[t] = (float)(1.0 / sqrt(v + 1e-5));
    }
}

__global__ void finalize2_kernel() {
    int t = threadIdx.x;
    if (t < OUTd) {
        double m = g_sum2[t] / (double)Nq;
        double v = g_sq2[t] / (double)Nq - m * m;
        if (v < 0) v = 0;
        g_mu2[t] = (float)m;
        g_rs2[t] = (float)(1.0 / sqrt(v + 1e-5));
    }
}

// ============ BN1 + output linear: z = outl_w @ BN1(x) + outl_b ============
__global__ __launch_bounds__(256) void proj_kernel(
    const float* __restrict__ outl_w, const float* __restrict__ outl_b,
    const float* __restrict__ norm_g, const float* __restrict__ norm_b)
{
    __shared__ float s_wt[64 * PAD];
    __shared__ float s_x[16 * 64];
    int tid = threadIdx.x;

    for (int i = tid; i < 64 * 64; i += 256) {
        int o = i >> 6, c = i & 63;
        s_wt[c * PAD + o] = outl_w[i];
    }
    int base = blockIdx.x * 16 * 64;
    for (int i = tid; i < 16 * 64; i += 256) {
        int c = i & 63;
        s_x[i] = (g_x[base + i] - g_mu1[c]) * g_rs1[c] * norm_g[c] + norm_b[c];
    }
    __syncthreads();

    int o = tid & 63;
    for (int rr = 0; rr < 4; ++rr) {
        int r = (tid >> 6) + rr * 4;
        const float* x = s_x + r * 64;
        float acc = outl_b[o];
        #pragma unroll
        for (int c = 0; c < 64; ++c) acc = fmaf(s_wt[c * PAD + o], x[c], acc);
        g_z[base + r * 64 + o] = acc;
    }
}

__global__ void final_kernel(float* __restrict__ out,
                             const float* __restrict__ obn_g,
                             const float* __restrict__ obn_b)
{
    int i = blockIdx.x * 256 + threadIdx.x;
    if (i < Nq * OUTd) {
        int o = i & 63;
        float v = (g_z[i] - g_mu2[o]) * g_rs2[o] * obn_g[o] + obn_b[o];
        out[i] = fmaxf(v, 0.f);
    }
}

extern "C" void kernel_launch(void* const* d_in, const int* in_sizes, int n_in,
                              void* d_out, int out_size) {
    const float* vf     = (const float*)d_in[0];
    const float* vc     = (const float*)d_in[1];
    const float* qcoord = (const float*)d_in[2];
    const int*   kidx   = (const int*)  d_in[3];
    const float* q_w    = (const float*)d_in[4];
    const float* q_b    = (const float*)d_in[5];
    const float* kpos_w = (const float*)d_in[6];
    const float* kpos_b = (const float*)d_in[7];
    const float* in_w   = (const float*)d_in[8];
    const float* in_b   = (const float*)d_in[9];
    const float* out_w  = (const float*)d_in[10];
    const float* out_b  = (const float*)d_in[11];
    const float* lin1_w = (const float*)d_in[12];
    const float* lin1_b = (const float*)d_in[13];
    const float* lin2_w = (const float*)d_in[14];
    const float* lin2_b = (const float*)d_in[15];
    const float* norm_g = (const float*)d_in[16];
    const float* norm_b = (const float*)d_in[17];
    const float* outl_w = (const float*)d_in[18];
    const float* outl_b = (const float*)d_in[19];
    const float* obn_g  = (const float*)d_in[20];
    const float* obn_b  = (const float*)d_in[21];
    float* out = (float*)d_out;

    cudaFuncSetAttribute(attn_kernel, cudaFuncAttributeMaxDynamicSharedMemorySize, SMEM_ATTN);
    cudaFuncSetAttribute(ffn_kernel,  cudaFuncAttributeMaxDynamicSharedMemorySize, SMEM_FFN);

    zero_stats<<<1, 64>>>();
    attn_kernel<<<Nq, 256, SMEM_ATTN>>>(vf, vc, qcoord, kidx, q_w, q_b, kpos_w, kpos_b,
                                        in_w, in_b, out_w, out_b);
    ffn_kernel<<<(Nq + FRPB - 1) / FRPB, 256, SMEM_FFN>>>(lin1_w, lin1_b, lin2_w, lin2_b);
    stats1_kernel<<<256, 256>>>();
    finalize1_kernel<<<1, 64>>>();
    proj_kernel<<<Nq / 16, 256>>>(outl_w, outl_b, norm_g, norm_b);
    stats2_kernel<<<256, 256>>>();
    finalize2_kernel<<<1, 64>>>();
    final_kernel<<<(Nq * OUTd + 255) / 256, 256>>>(out, obn_g, obn_b);
}

// round 4
// speedup vs baseline: 2.1747x; 1.2360x over previous
#include <cuda_runtime.h>
#include <math.h>

#define Nq   20000
#define KK   48
#define Cdim 64
#define FFd  256
#define Hh   4
#define OUTd 64
#define NQB  3

typedef unsigned long long ull;

// ---- scratch ----
__device__ float  g_att[Nq * Cdim];
__device__ float  g_x[Nq * Cdim];
__device__ float  g_z[Nq * OUTd];
__device__ double g_sum1[Cdim], g_sq1[Cdim];
__device__ double g_sum2[OUTd], g_sq2[OUTd];
__device__ float  g_mu1[Cdim], g_rs1[Cdim];
__device__ float  g_mu2[OUTd], g_rs2[OUTd];

// ---- f32x2 packed math ----
__device__ __forceinline__ ull pk2(float lo, float hi) {
    ull r; asm("mov.b64 %0, {%1, %2};" : "=l"(r) : "f"(lo), "f"(hi)); return r;
}
__device__ __forceinline__ void upk2(ull v, float& lo, float& hi) {
    asm("mov.b64 {%0, %1}, %2;" : "=f"(lo), "=f"(hi) : "l"(v));
}
__device__ __forceinline__ ull fma2(ull a, ull b, ull c) {
    ull d; asm("fma.rn.f32x2 %0, %1, %2, %3;" : "=l"(d) : "l"(a), "l"(b), "l"(c)); return d;
}
__device__ __forceinline__ ull add2(ull a, ull b) {
    ull d; asm("add.rn.f32x2 %0, %1, %2;" : "=l"(d) : "l"(a), "l"(b)); return d;
}

__global__ void zero_stats() {
    int t = threadIdx.x;
    if (t < Cdim) { g_sum1[t] = 0.0; g_sq1[t] = 0.0; }
    if (t < OUTd) { g_sum2[t] = 0.0; g_sq2[t] = 0.0; }
}

// ===================== attention kernel: NQB queries per block, 192 threads =====================
// dyn smem (floats unless noted):
//  s_wkvT ull[64*64]            32768 B
//  s_kf   f[NQB*48*65]          37440 B   (aliased as s_vp after GEMM)
//  s_wqT  f[64*65]              16640 B
//  s_woT  f[64*65]              16640 B
//  s_qf f[192], s_q f[192], s_sc f[NQB*4*48], s_ctx f[192], s_rel f[NQB*48*4], s_idx int[NQB*48]
#define SM_WKV   0
#define SM_KF    (4096)                       // ull index base for floats below (cast)
#define SMEM_ATTN (32768 + 37440 + 16640 + 16640 + 768 + 768 + 2304 + 768 + 2304 + 576)

__global__ __launch_bounds__(192, 2) void attn_kernel(
    const float* __restrict__ vf,     const float* __restrict__ vc,
    const float* __restrict__ qc,     const int*   __restrict__ kidx,
    const float* __restrict__ q_w,    const float* __restrict__ q_b,
    const float* __restrict__ kpos_w, const float* __restrict__ kpos_b,
    const float* __restrict__ in_w,   const float* __restrict__ in_b,
    const float* __restrict__ out_w,  const float* __restrict__ out_b)
{
    extern __shared__ char smem[];
    ull*   s_wkvT = (ull*)smem;                         // 4096 ull
    float* s_kf   = (float*)(s_wkvT + 4096);            // 9360 f  (alias s_vp)
    float* s_wqT  = s_kf + NQB * 48 * 65;               // 4160 f
    float* s_woT  = s_wqT + 4160;                       // 4160 f
    float* s_qf   = s_woT + 4160;                       // 192
    float* s_q    = s_qf + 192;                         // 192
    float* s_sc   = s_q + 192;                          // 576
    float* s_ctx  = s_sc + NQB * 4 * 48;                // 192
    float* s_rel  = s_ctx + 192;                        // 576
    int*   s_idx  = (int*)(s_rel + NQB * 48 * 4);       // 144

    const int tid  = threadIdx.x;
    const int lane = tid & 31;
    const int warp = tid >> 5;
    const int n0   = blockIdx.x * NQB;

    // ---------------- phase 1: staging (no deps) ----------------
    // stage (Wk,Wv) interleaved transposed: s_wkvT[j*64 + c]
    for (int i = tid; i < 1024; i += 192) {
        int j4 = i & 15, c = i >> 4;
        float4 k4 = *(const float4*)(in_w + (64  + c) * 64 + j4 * 4);
        float4 v4 = *(const float4*)(in_w + (128 + c) * 64 + j4 * 4);
        s_wkvT[(j4*4+0)*64 + c] = pk2(k4.x, v4.x);
        s_wkvT[(j4*4+1)*64 + c] = pk2(k4.y, v4.y);
        s_wkvT[(j4*4+2)*64 + c] = pk2(k4.z, v4.z);
        s_wkvT[(j4*4+3)*64 + c] = pk2(k4.w, v4.w);
    }
    // stage Wq^T and out_w^T (padded 65)
    for (int i = tid; i < 4096; i += 192) {
        int c = i >> 6, j = i & 63;
        s_wqT[j * 65 + c] = in_w[i];       // rows 0..63 of in_w = Wq
        s_woT[j * 65 + c] = out_w[i];
    }
    // key indices + relative coords
    if (tid < NQB * KK) {
        int q = tid / KK, kk = tid - q * KK;
        int n = n0 + q; if (n >= Nq) n = Nq - 1;
        int idx = kidx[n * KK + kk];
        s_idx[tid] = idx;
        int safe = idx < 0 ? 0 : idx;
        s_rel[tid * 4 + 0] = vc[safe * 3 + 0] - qc[n * 3 + 0];
        s_rel[tid * 4 + 1] = vc[safe * 3 + 1] - qc[n * 3 + 1];
        s_rel[tid * 4 + 2] = vc[safe * 3 + 2] - qc[n * 3 + 2];
    }
    // query positional features
    {
        int q = tid >> 6, c = tid & 63;
        int n = n0 + q; if (n >= Nq) n = Nq - 1;
        float a = q_b[c] + q_w[c*3]*qc[n*3] + q_w[c*3+1]*qc[n*3+1] + q_w[c*3+2]*qc[n*3+2];
        s_qf[tid] = fmaxf(a, 0.f);
    }
    __syncthreads();

    // ---------------- phase 2: kf fill + q projection ----------------
    {
        const int c = tid & 63;           // fixed per thread (192 % 64 == 0)
        const float kw0 = kpos_w[c*3], kw1 = kpos_w[c*3+1], kw2 = kpos_w[c*3+2];
        const float kb  = kpos_b[c];
        for (int e = tid; e < NQB * KK * 64; e += 192) {
            int kg = e >> 6;              // (q*48+kk)
            int idx = s_idx[kg]; if (idx < 0) idx = 0;
            float f = vf[idx * 64 + c];
            float p = kb + kw0 * s_rel[kg*4] + kw1 * s_rel[kg*4+1] + kw2 * s_rel[kg*4+2];
            s_kf[kg * 65 + c] = f + fmaxf(p, 0.f);
        }
    }
    {
        int q = tid >> 6, c = tid & 63;
        float acc = 0.f;
        const float* qf = s_qf + q * 64;
        #pragma unroll 8
        for (int j = 0; j < 64; ++j) acc = fmaf(s_wqT[j * 65 + c], qf[j], acc);
        s_q[tid] = (acc + in_b[c]) * 0.25f;
    }
    __syncthreads();

    // ---------------- phase 3: K/V GEMM, 6kk x 8c tile, packed (K,V) ----------------
    const int q_  = tid >> 6;
    const int sub = tid & 63;
    const int kk0 = (sub >> 3) * 6;
    const int c0  = (sub & 7) * 8;

    ull acc[6][8];
    #pragma unroll
    for (int u = 0; u < 8; ++u) {
        ull b = pk2(in_b[64 + c0 + u], in_b[128 + c0 + u]);
        #pragma unroll
        for (int i = 0; i < 6; ++i) acc[i][u] = b;
    }
    {
        const float* kfb = s_kf + (q_ * 48 + kk0) * 65;
        #pragma unroll 2
        for (int j = 0; j < 64; ++j) {
            ull F[6];
            #pragma unroll
            for (int i = 0; i < 6; ++i) { float f = kfb[i * 65 + j]; F[i] = pk2(f, f); }
            const ull* wr = s_wkvT + j * 64 + c0;
            ulonglong2 wa = *(const ulonglong2*)(wr);
            ulonglong2 wb = *(const ulonglong2*)(wr + 2);
            ulonglong2 wc = *(const ulonglong2*)(wr + 4);
            ulonglong2 wd = *(const ulonglong2*)(wr + 6);
            #pragma unroll
            for (int i = 0; i < 6; ++i) {
                acc[i][0] = fma2(wa.x, F[i], acc[i][0]);
                acc[i][1] = fma2(wa.y, F[i], acc[i][1]);
                acc[i][2] = fma2(wb.x, F[i], acc[i][2]);
                acc[i][3] = fma2(wb.y, F[i], acc[i][3]);
                acc[i][4] = fma2(wc.x, F[i], acc[i][4]);
                acc[i][5] = fma2(wc.y, F[i], acc[i][5]);
                acc[i][6] = fma2(wd.x, F[i], acc[i][6]);
                acc[i][7] = fma2(wd.y, F[i], acc[i][7]);
            }
        }
    }
    // scores from K-half of accs; partner (cg^1) completes the head
    {
        const int h = (sub & 7) >> 1;
        #pragma unroll
        for (int i = 0; i < 6; ++i) {
            float part = 0.f;
            #pragma unroll
            for (int u = 0; u < 8; ++u) {
                float kp, vp; upk2(acc[i][u], kp, vp);
                part = fmaf(kp, s_q[q_ * 64 + c0 + u], part);
            }
            float tot = part + __shfl_xor_sync(0xffffffffu, part, 1);
            if ((sub & 1) == 0) {
                int kk = kk0 + i;
                s_sc[(q_ * 4 + h) * 48 + kk] = (s_idx[q_ * 48 + kk] < 0) ? -1e30f : tot;
            }
        }
    }
    __syncthreads();   // kf dead, scores complete

    // ---------------- phase 4: vp store (alias kf) + softmax ----------------
    {
        float* s_vp = s_kf;
        #pragma unroll
        for (int i = 0; i < 6; ++i)
            #pragma unroll
            for (int u = 0; u < 8; ++u) {
                float kp, vp; upk2(acc[i][u], kp, vp);
                s_vp[(q_ * 48 + kk0 + i) * 65 + c0 + u] = vp;
            }
    }
    for (int r = warp; r < NQB * 4; r += 6) {
        float* sc = s_sc + r * 48;
        float v0 = sc[lane];
        float v1 = (lane < 16) ? sc[32 + lane] : -1e30f;
        float m = fmaxf(v0, v1);
        #pragma unroll
        for (int o = 16; o > 0; o >>= 1) m = fmaxf(m, __shfl_xor_sync(0xffffffffu, m, o));
        float e0 = __expf(v0 - m);
        float e1 = (lane < 16) ? __expf(v1 - m) : 0.f;
        float s = e0 + e1;
        #pragma unroll
        for (int o = 16; o > 0; o >>= 1) s += __shfl_xor_sync(0xffffffffu, s, o);
        float inv = 1.f / s;
        sc[lane] = e0 * inv;
        if (lane < 16) sc[32 + lane] = e1 * inv;
    }
    __syncthreads();

    // ---------------- phase 5: ctx = attn @ V ----------------
    {
        int q = tid >> 6, c = tid & 63, h = c >> 4;
        const float* a  = s_sc + (q * 4 + h) * 48;
        const float* vp = s_kf + (q * 48) * 65 + c;
        float acc2 = 0.f;
        #pragma unroll 8
        for (int kk = 0; kk < KK; ++kk) acc2 = fmaf(a[kk], vp[kk * 65], acc2);
        s_ctx[tid] = acc2;
    }
    __syncthreads();

    // ---------------- phase 6: att = out_w @ ctx + out_b ----------------
    {
        int q = tid >> 6, c = tid & 63;
        float acc3 = 0.f;
        const float* cx = s_ctx + q * 64;
        #pragma unroll 8
        for (int j = 0; j < 64; ++j) acc3 = fmaf(s_woT[j * 65 + c], cx[j], acc3);
        int n = n0 + q;
        if (n < Nq) g_att[n * 64 + c] = acc3 + out_b[c];
    }
}

// ================= FFN kernel (+fused BN1 stats): x = att + lin2(relu(lin1 att)) =================
#define FRPB 136
#define W1PAD 258
#define W2PAD 66
#define SMEM_FFN ((128 + 512 + 256) * 8 + (64 * W1PAD + 256 * W2PAD) * 4)

__global__ __launch_bounds__(256) void ffn_kernel(
    const float* __restrict__ lin1_w, const float* __restrict__ lin1_b,
    const float* __restrict__ lin2_w, const float* __restrict__ lin2_b)
{
    extern __shared__ char smem[];
    ull*   s_att2 = (ull*)smem;            // [2][64]
    ull*   s_h2   = s_att2 + 128;          // [2][256]
    ull*   s_red  = s_h2 + 512;            // [256]
    float* s_w1t  = (float*)(s_red + 256); // [64][258]
    float* s_w2t  = s_w1t + 64 * W1PAD;    // [256][66]

    const int tid = threadIdx.x;

    for (int i = tid; i < FFd * Cdim; i += 256) {
        int f = i >> 6, j = i & 63;
        s_w1t[j * W1PAD + f] = lin1_w[i];
    }
    for (int i = tid; i < Cdim * FFd; i += 256) {
        int c = i >> 8, j = i & 255;
        s_w2t[j * W2PAD + c] = lin2_w[i];
    }
    const int p_ = tid & 127;
    const ull bias1 = pk2(lin1_b[2 * p_], lin1_b[2 * p_ + 1]);

    float ps0 = 0.f, pq0 = 0.f, ps1 = 0.f, pq1 = 0.f;   // BN1 stats partials

    const int r0 = blockIdx.x * FRPB;
    for (int it = 0; it < FRPB / 2; ++it) {
        const int row0 = r0 + it * 2;
        __syncthreads();
        if (tid < 128) {
            int r = tid >> 6, j = tid & 63;
            int row = row0 + r;
            float v = (row < Nq) ? g_att[row * 64 + j] : 0.f;
            s_att2[r * 64 + j] = pk2(v, v);
        }
        __syncthreads();
        {
            int r = tid >> 7, p = tid & 127;
            ull acc = bias1;
            #pragma unroll 8
            for (int j = 0; j < 64; ++j)
                acc = fma2(((const ull*)(s_w1t + j * W1PAD))[p], s_att2[r * 64 + j], acc);
            float h0, h1; upk2(acc, h0, h1);
            h0 = fmaxf(h0, 0.f); h1 = fmaxf(h1, 0.f);
            s_h2[r * 256 + 2 * p]     = pk2(h0, h0);
            s_h2[r * 256 + 2 * p + 1] = pk2(h1, h1);
        }
        __syncthreads();
        {
            int r = tid >> 7, s = (tid >> 5) & 3, cp = tid & 31;
            ull acc = 0;
            int j0 = s * 64;
            #pragma unroll 8
            for (int j = 0; j < 64; ++j)
                acc = fma2(((const ull*)(s_w2t + (j0 + j) * W2PAD))[cp],
                           s_h2[r * 256 + j0 + j], acc);
            s_red[tid] = acc;
        }
        __syncthreads();
        if (tid < 64) {
            int r = tid >> 5, cp = tid & 31;
            ull a = add2(add2(s_red[r * 128 + cp],      s_red[r * 128 + 32 + cp]),
                         add2(s_red[r * 128 + 64 + cp], s_red[r * 128 + 96 + cp]));
            float x0, x1; upk2(a, x0, x1);
            float a0, t; upk2(s_att2[r * 64 + 2 * cp], a0, t);
            float a1;    upk2(s_att2[r * 64 + 2 * cp + 1], a1, t);
            int row = row0 + r;
            if (row < Nq) {
                float2 o;
                o.x = a0 + x0 + lin2_b[2 * cp];
                o.y = a1 + x1 + lin2_b[2 * cp + 1];
                *(float2*)(g_x + row * 64 + 2 * cp) = o;
                ps0 += o.x; pq0 += o.x * o.x;
                ps1 += o.y; pq1 += o.y * o.y;
            }
        }
    }
    if (tid < 64) {
        int cp = tid & 31;
        atomicAdd(&g_sum1[2 * cp],     (double)ps0);
        atomicAdd(&g_sq1 [2 * cp],     (double)pq0);
        atomicAdd(&g_sum1[2 * cp + 1], (double)ps1);
        atomicAdd(&g_sq1 [2 * cp + 1], (double)pq1);
    }
}

__global__ void finalize1_kernel() {
    int t = threadIdx.x;
    if (t < Cdim) {
        double m = g_sum1[t] / (double)Nq;
        double v = g_sq1[t] / (double)Nq - m * m;
        if (v < 0) v = 0;
        g_mu1[t] = (float)m;
        g_rs1[t] = (float)(1.0 / sqrt(v + 1e-5));
    }
}

__global__ void finalize2_kernel() {
    int t = threadIdx.x;
    if (t < OUTd) {
        double m = g_sum2[t] / (double)Nq;
        double v = g_sq2[t] / (double)Nq - m * m;
        if (v < 0) v = 0;
        g_mu2[t] = (float)m;
        g_rs2[t] = (float)(1.0 / sqrt(v + 1e-5));
    }
}

// ============ BN1 + output linear (+fused BN2 stats) ============
__global__ __launch_bounds__(256) void proj_kernel(
    const float* __restrict__ outl_w, const float* __restrict__ outl_b,
    const float* __restrict__ norm_g, const float* __restrict__ norm_b)
{
    __shared__ float s_wt[64 * 65];
    __shared__ float s_x[16 * 64];
    __shared__ float s_ps[64], s_pq[64];
    int tid = threadIdx.x;

    if (tid < 64) { s_ps[tid] = 0.f; s_pq[tid] = 0.f; }
    for (int i = tid; i < 64 * 64; i += 256) {
        int o = i >> 6, c = i & 63;
        s_wt[c * 65 + o] = outl_w[i];
    }
    int base = blockIdx.x * 16 * 64;
    for (int i = tid; i < 16 * 64; i += 256) {
        int c = i & 63;
        s_x[i] = (g_x[base + i] - g_mu1[c]) * g_rs1[c] * norm_g[c] + norm_b[c];
    }
    __syncthreads();

    int o = tid & 63;
    float zs = 0.f, zq = 0.f;
    for (int rr = 0; rr < 4; ++rr) {
        int r = (tid >> 6) + rr * 4;
        const float* x = s_x + r * 64;
        float acc = outl_b[o];
        #pragma unroll
        for (int c = 0; c < 64; ++c) acc = fmaf(s_wt[c * 65 + o], x[c], acc);
        g_z[base + r * 64 + o] = acc;
        zs += acc; zq += acc * acc;
    }
    atomicAdd(&s_ps[o], zs);
    atomicAdd(&s_pq[o], zq);
    __syncthreads();
    if (tid < 64) {
        atomicAdd(&g_sum2[tid], (double)s_ps[tid]);
        atomicAdd(&g_sq2[tid],  (double)s_pq[tid]);
    }
}

__global__ void final_kernel(float* __restrict__ out,
                             const float* __restrict__ obn_g,
                             const float* __restrict__ obn_b)
{
    int i = blockIdx.x * 256 + threadIdx.x;
    if (i < Nq * OUTd) {
        int o = i & 63;
        float v = (g_z[i] - g_mu2[o]) * g_rs2[o] * obn_g[o] + obn_b[o];
        out[i] = fmaxf(v, 0.f);
    }
}

extern "C" void kernel_launch(void* const* d_in, const int* in_sizes, int n_in,
                              void* d_out, int out_size) {
    const float* vf     = (const float*)d_in[0];
    const float* vc     = (const float*)d_in[1];
    const float* qcoord = (const float*)d_in[2];
    const int*   kidx   = (const int*)  d_in[3];
    const float* q_w    = (const float*)d_in[4];
    const float* q_b    = (const float*)d_in[5];
    const float* kpos_w = (const float*)d_in[6];
    const float* kpos_b = (const float*)d_in[7];
    const float* in_w   = (const float*)d_in[8];
    const float* in_b   = (const float*)d_in[9];
    const float* out_w  = (const float*)d_in[10];
    const float* out_b  = (const float*)d_in[11];
    const float* lin1_w = (const float*)d_in[12];
    const float* lin1_b = (const float*)d_in[13];
    const float* lin2_w = (const float*)d_in[14];
    const float* lin2_b = (const float*)d_in[15];
    const float* norm_g = (const float*)d_in[16];
    const float* norm_b = (const float*)d_in[17];
    const float* outl_w = (const float*)d_in[18];
    const float* outl_b = (const float*)d_in[19];
    const float* obn_g  = (const float*)d_in[20];
    const float* obn_b  = (const float*)d_in[21];
    float* out = (float*)d_out;

    cudaFuncSetAttribute(attn_kernel, cudaFuncAttributeMaxDynamicSharedMemorySize, SMEM_ATTN);
    cudaFuncSetAttribute(ffn_kernel,  cudaFuncAttributeMaxDynamicSharedMemorySize, SMEM_FFN);

    zero_stats<<<1, 64>>>();
    attn_kernel<<<(Nq + NQB - 1) / NQB, 192, SMEM_ATTN>>>(
        vf, vc, qcoord, kidx, q_w, q_b, kpos_w, kpos_b, in_w, in_b, out_w, out_b);
    ffn_kernel<<<(Nq + FRPB - 1) / FRPB, 256, SMEM_FFN>>>(lin1_w, lin1_b, lin2_w, lin2_b);
    finalize1_kernel<<<1, 64>>>();
    proj_kernel<<<Nq / 16, 256>>>(outl_w, outl_b, norm_g, norm_b);
    finalize2_kernel<<<1, 64>>>();
    final_kernel<<<(Nq * OUTd + 255) / 256, 256>>>(out, obn_g, obn_b);
}

// round 5
// speedup vs baseline: 3.4511x; 1.5870x over previous
#include <cuda_runtime.h>
#include <math.h>

#define Nq   20000
#define KK   48
#define Cdim 64
#define FFd  256
#define OUTd 64
#define NQB  2          // queries per attn block
#define PADK 68         // kf row pad (floats)
#define PADN 132        // B row pad (floats)

typedef unsigned long long ull;

// ---- scratch ----
__device__ float  g_q[Nq * Cdim];     // scaled q vectors
__device__ float  g_ctx[Nq * Cdim];   // attention context (pre out-proj)
__device__ float  g_x[Nq * Cdim];     // pre-BN1 activations
__device__ float  g_z[Nq * OUTd];     // pre-BN2 activations
__device__ double g_sum1[Cdim], g_sq1[Cdim];
__device__ double g_sum2[OUTd], g_sq2[OUTd];
__device__ float  g_mu1[Cdim], g_rs1[Cdim];
__device__ float  g_mu2[OUTd], g_rs2[OUTd];

// ---- f32x2 packed math ----
__device__ __forceinline__ ull pk2(float lo, float hi) {
    ull r; asm("mov.b64 %0, {%1, %2};" : "=l"(r) : "f"(lo), "f"(hi)); return r;
}
__device__ __forceinline__ void upk2(ull v, float& lo, float& hi) {
    asm("mov.b64 {%0, %1}, %2;" : "=f"(lo), "=f"(hi) : "l"(v));
}
__device__ __forceinline__ ull fma2(ull a, ull b, ull c) {
    ull d; asm("fma.rn.f32x2 %0, %1, %2, %3;" : "=l"(d) : "l"(a), "l"(b), "l"(c)); return d;
}
__device__ __forceinline__ ull add2(ull a, ull b) {
    ull d; asm("add.rn.f32x2 %0, %1, %2;" : "=l"(d) : "l"(a), "l"(b)); return d;
}
__device__ __forceinline__ unsigned f2tf32(float x) {
    unsigned r; asm("cvt.rna.tf32.f32 %0, %1;" : "=r"(r) : "f"(x)); return r;
}
__device__ __forceinline__ void mma_tf32(float& d0, float& d1, float& d2, float& d3,
                                         unsigned a0, unsigned a1, unsigned a2, unsigned a3,
                                         unsigned b0, unsigned b1) {
    asm volatile("mma.sync.aligned.m16n8k8.row.col.f32.tf32.tf32.f32 "
                 "{%0,%1,%2,%3}, {%4,%5,%6,%7}, {%8,%9}, {%0,%1,%2,%3};"
                 : "+f"(d0), "+f"(d1), "+f"(d2), "+f"(d3)
                 : "r"(a0), "r"(a1), "r"(a2), "r"(a3), "r"(b0), "r"(b1));
}

__global__ void zero_stats() {
    int t = threadIdx.x;
    if (t < Cdim) { g_sum1[t] = 0.0; g_sq1[t] = 0.0; }
    if (t < OUTd) { g_sum2[t] = 0.0; g_sq2[t] = 0.0; }
}

// ===================== q projection: q = (Wq relu(qw qc + qb) + bq)/4 =====================
#define QRPB 100
__global__ __launch_bounds__(256) void qproj_kernel(
    const float* __restrict__ qc, const float* __restrict__ q_w, const float* __restrict__ q_b,
    const float* __restrict__ in_w, const float* __restrict__ in_b)
{
    __shared__ float s_wqT[64 * 65];
    __shared__ float s_qf[4][64];
    const int tid = threadIdx.x;
    for (int i = tid; i < 4096; i += 256) {
        int c = i >> 6, j = i & 63;
        s_wqT[j * 65 + c] = in_w[i];
    }
    __syncthreads();
    const int r = tid >> 6, c = tid & 63;
    const float w0 = q_w[c * 3], w1 = q_w[c * 3 + 1], w2 = q_w[c * 3 + 2], b = q_b[c];
    const int base0 = blockIdx.x * QRPB;
    for (int it = 0; it < QRPB / 4; ++it) {
        int row = base0 + it * 4 + r;
        float qf = 0.f;
        if (row < Nq)
            qf = fmaxf(b + w0 * qc[row*3] + w1 * qc[row*3+1] + w2 * qc[row*3+2], 0.f);
        s_qf[r][c] = qf;
        __syncthreads();
        float acc = 0.f;
        #pragma unroll 8
        for (int j = 0; j < 64; ++j) acc = fmaf(s_wqT[j * 65 + c], s_qf[r][j], acc);
        if (row < Nq) g_q[row * 64 + c] = (acc + in_b[c]) * 0.25f;
        __syncthreads();
    }
}

// ===================== attention kernel: 2 queries/block, tf32 mma K/V GEMM =====================
// smem floats: kf 96*68 | B 64*132 | q 128 | sc 384 | rel 288 | idx 96(int)
#define SMEM_ATTN ((96*PADK + 64*PADN + 128 + 384 + 288 + 96) * 4)

__global__ __launch_bounds__(192, 2) void attn_kernel(
    const float* __restrict__ vf,     const float* __restrict__ vc,
    const float* __restrict__ qc,     const int*   __restrict__ kidx,
    const float* __restrict__ kpos_w, const float* __restrict__ kpos_b,
    const float* __restrict__ in_w,   const float* __restrict__ in_b)
{
    extern __shared__ char smem[];
    float* s_kf  = (float*)smem;                 // 96*68   (alias: vp after MMA)
    float* s_B   = s_kf + 96 * PADK;             // 64*132  (tf32-rounded Wkv [k][n])
    float* s_q   = s_B + 64 * PADN;              // 128
    float* s_sc  = s_q + 128;                    // 2*4*48
    float* s_rel = s_sc + 384;                   // 96*3
    int*   s_idx = (int*)(s_rel + 288);          // 96

    const int tid  = threadIdx.x;
    const int lane = tid & 31;
    const int w    = tid >> 5;            // warp 0..5
    const int n0   = blockIdx.x * NQB;

    // ---- phase 1: stage B (Wk|Wv as [k][n], tf32-rounded), idx/rel, q ----
    for (int i = tid; i < 8192; i += 192) {
        int n = i >> 6, k = i & 63;
        ((unsigned*)s_B)[k * PADN + n] = f2tf32(in_w[4096 + i]);
    }
    if (tid < 96) {
        int q = tid / KK, kk = tid - q * KK;
        int n = n0 + q;
        int idx = kidx[n * KK + kk];
        s_idx[tid] = idx;
        int safe = idx < 0 ? 0 : idx;
        s_rel[tid * 3 + 0] = vc[safe * 3 + 0] - qc[n * 3 + 0];
        s_rel[tid * 3 + 1] = vc[safe * 3 + 1] - qc[n * 3 + 1];
        s_rel[tid * 3 + 2] = vc[safe * 3 + 2] - qc[n * 3 + 2];
    }
    if (tid < 128) s_q[tid] = g_q[(n0 + (tid >> 6)) * 64 + (tid & 63)];
    __syncthreads();

    // ---- phase 2: gather key features (tf32-rounded) ----
    {
        const int c = tid & 63;
        const float kw0 = kpos_w[c*3], kw1 = kpos_w[c*3+1], kw2 = kpos_w[c*3+2];
        const float kb  = kpos_b[c];
        for (int e = tid; e < 96 * 64; e += 192) {
            int kg = e >> 6;
            int idx = s_idx[kg]; if (idx < 0) idx = 0;
            float f = vf[idx * 64 + c];
            float p = kb + kw0 * s_rel[kg*3] + kw1 * s_rel[kg*3+1] + kw2 * s_rel[kg*3+2];
            ((unsigned*)s_kf)[kg * PADK + c] = f2tf32(f + fmaxf(p, 0.f));
        }
    }
    __syncthreads();

    // ---- phase 3: MMA  D[96,128] = kf[96,64] @ B[64,128] ----
    const int g   = lane >> 2;      // 0..7
    const int tig = lane & 3;       // 0..3
    const int mr  = w * 16;

    float acc[16][4];
    #pragma unroll
    for (int nt = 0; nt < 16; ++nt)
        #pragma unroll
        for (int j = 0; j < 4; ++j) acc[nt][j] = 0.f;

    {
        const unsigned* kfu = (const unsigned*)s_kf;
        const unsigned* Bu  = (const unsigned*)s_B;
        const unsigned* arow0 = kfu + (mr + g) * PADK + tig;
        const unsigned* arow1 = kfu + (mr + g + 8) * PADK + tig;
        #pragma unroll
        for (int ks = 0; ks < 8; ++ks) {
            const int k0 = ks * 8;
            unsigned a0 = arow0[k0], a2 = arow0[k0 + 4];
            unsigned a1 = arow1[k0], a3 = arow1[k0 + 4];
            const unsigned* b0p = Bu + (k0 + tig) * PADN + g;
            const unsigned* b1p = Bu + (k0 + tig + 4) * PADN + g;
            #pragma unroll
            for (int nt = 0; nt < 16; ++nt) {
                unsigned b0 = b0p[nt * 8];
                unsigned b1 = b1p[nt * 8];
                mma_tf32(acc[nt][0], acc[nt][1], acc[nt][2], acc[nt][3],
                         a0, a1, a2, a3, b0, b1);
            }
        }
    }
    // K bias
    #pragma unroll
    for (int nt = 0; nt < 8; ++nt) {
        int cc = 8 * nt + 2 * tig;
        float b0 = in_b[64 + cc], b1 = in_b[64 + cc + 1];
        acc[nt][0] += b0; acc[nt][1] += b1;
        acc[nt][2] += b0; acc[nt][3] += b1;
    }
    // ---- scores from K fragments (quad reduce), write s_sc ----
    {
        const int qsel = (w >= 3);
        const int qb = qsel * 64;
        const int keyb = (w - qsel * 3) * 16 + g;
        #pragma unroll
        for (int h = 0; h < 4; ++h) {
            int nA = 2 * h, nB = 2 * h + 1;
            int cA = 8 * nA + 2 * tig, cB = 8 * nB + 2 * tig;
            float qA0 = s_q[qb + cA], qA1 = s_q[qb + cA + 1];
            float qB0 = s_q[qb + cB], qB1 = s_q[qb + cB + 1];
            float s0 = acc[nA][0]*qA0 + acc[nA][1]*qA1 + acc[nB][0]*qB0 + acc[nB][1]*qB1;
            float s1 = acc[nA][2]*qA0 + acc[nA][3]*qA1 + acc[nB][2]*qB0 + acc[nB][3]*qB1;
            s0 += __shfl_xor_sync(0xffffffffu, s0, 1);
            s0 += __shfl_xor_sync(0xffffffffu, s0, 2);
            s1 += __shfl_xor_sync(0xffffffffu, s1, 1);
            s1 += __shfl_xor_sync(0xffffffffu, s1, 2);
            if (tig == 0) {
                int rbase = qsel * 48 + keyb;
                s_sc[(qsel * 4 + h) * 48 + keyb]     = (s_idx[rbase]     < 0) ? -1e30f : s0;
                s_sc[(qsel * 4 + h) * 48 + keyb + 8] = (s_idx[rbase + 8] < 0) ? -1e30f : s1;
            }
        }
    }
    __syncthreads();   // kf dead; scores complete

    // ---- phase 4: V -> smem (alias kf) + softmax ----
    {
        float* s_vp = s_kf;
        const int row0 = mr + g;
        #pragma unroll
        for (int nt = 8; nt < 16; ++nt) {
            int cc = 8 * (nt - 8) + 2 * tig;
            float b0 = in_b[128 + cc], b1 = in_b[128 + cc + 1];
            s_vp[row0 * PADK + cc]           = acc[nt][0] + b0;
            s_vp[row0 * PADK + cc + 1]       = acc[nt][1] + b1;
            s_vp[(row0 + 8) * PADK + cc]     = acc[nt][2] + b0;
            s_vp[(row0 + 8) * PADK + cc + 1] = acc[nt][3] + b1;
        }
    }
    for (int r = w; r < 8; r += 6) {
        float* sc = s_sc + r * 48;
        float v0 = sc[lane];
        float v1 = (lane < 16) ? sc[32 + lane] : -1e30f;
        float m = fmaxf(v0, v1);
        #pragma unroll
        for (int o = 16; o > 0; o >>= 1) m = fmaxf(m, __shfl_xor_sync(0xffffffffu, m, o));
        float e0 = __expf(v0 - m);
        float e1 = (lane < 16) ? __expf(v1 - m) : 0.f;
        float s = e0 + e1;
        #pragma unroll
        for (int o = 16; o > 0; o >>= 1) s += __shfl_xor_sync(0xffffffffu, s, o);
        float inv = 1.f / s;
        sc[lane] = e0 * inv;
        if (lane < 16) sc[32 + lane] = e1 * inv;
    }
    __syncthreads();

    // ---- phase 5: ctx = attn @ V -> g_ctx ----
    if (tid < 128) {
        int q = tid >> 6, c = tid & 63, h = c >> 4;
        const float* a  = s_sc + (q * 4 + h) * 48;
        const float* vp = s_kf + (q * 48) * PADK + c;
        float acc2 = 0.f;
        #pragma unroll 8
        for (int kk = 0; kk < KK; ++kk) acc2 = fmaf(a[kk], vp[kk * PADK], acc2);
        g_ctx[(n0 + q) * 64 + c] = acc2;
    }
}

// ============ FFN kernel (+out-proj, +fused BN1 stats) ============
#define FRPB 136
#define W1PAD 258
#define W2PAD 66
#define SMEM_FFN ((128 + 512 + 256) * 8 + (64 * W1PAD + 256 * W2PAD + 64 * 65 + 128) * 4)

__global__ __launch_bounds__(256) void ffn_kernel(
    const float* __restrict__ out_w,  const float* __restrict__ out_b,
    const float* __restrict__ lin1_w, const float* __restrict__ lin1_b,
    const float* __restrict__ lin2_w, const float* __restrict__ lin2_b)
{
    extern __shared__ char smem[];
    ull*   s_att2 = (ull*)smem;             // [2][64]
    ull*   s_h2   = s_att2 + 128;           // [2][256]
    ull*   s_red  = s_h2 + 512;             // [256]
    float* s_w1t  = (float*)(s_red + 256);  // [64][258]
    float* s_w2t  = s_w1t + 64 * W1PAD;     // [256][66]
    float* s_woT  = s_w2t + 256 * W2PAD;    // [64][65]
    float* s_ctx2 = s_woT + 64 * 65;        // [2][64]

    const int tid = threadIdx.x;

    for (int i = tid; i < FFd * Cdim; i += 256) {
        int f = i >> 6, j = i & 63;
        s_w1t[j * W1PAD + f] = lin1_w[i];
    }
    for (int i = tid; i < Cdim * FFd; i += 256) {
        int c = i >> 8, j = i & 255;
        s_w2t[j * W2PAD + c] = lin2_w[i];
    }
    for (int i = tid; i < 4096; i += 256) {
        int o = i >> 6, j = i & 63;
        s_woT[j * 65 + o] = out_w[i];
    }
    const int p_ = tid & 127;
    const ull bias1 = pk2(lin1_b[2 * p_], lin1_b[2 * p_ + 1]);

    float ps0 = 0.f, pq0 = 0.f, ps1 = 0.f, pq1 = 0.f;

    const int r0 = blockIdx.x * FRPB;
    for (int it = 0; it < FRPB / 2; ++it) {
        const int row0 = r0 + it * 2;
        __syncthreads();
        if (tid < 128) {
            int r = tid >> 6, j = tid & 63;
            int row = row0 + r;
            s_ctx2[r * 64 + j] = (row < Nq) ? g_ctx[row * 64 + j] : 0.f;
        }
        __syncthreads();
        if (tid < 128) {                     // att = out_w @ ctx + out_b
            int r = tid >> 6, o = tid & 63;
            float acc = out_b[o];
            #pragma unroll 8
            for (int j = 0; j < 64; ++j) acc = fmaf(s_woT[j * 65 + o], s_ctx2[r * 64 + j], acc);
            s_att2[r * 64 + o] = pk2(acc, acc);
        }
        __syncthreads();
        {
            int r = tid >> 7, p = tid & 127;
            ull acc = bias1;
            #pragma unroll 8
            for (int j = 0; j < 64; ++j)
                acc = fma2(((const ull*)(s_w1t + j * W1PAD))[p], s_att2[r * 64 + j], acc);
            float h0, h1; upk2(acc, h0, h1);
            h0 = fmaxf(h0, 0.f); h1 = fmaxf(h1, 0.f);
            s_h2[r * 256 + 2 * p]     = pk2(h0, h0);
            s_h2[r * 256 + 2 * p + 1] = pk2(h1, h1);
        }
        __syncthreads();
        {
            int r = tid >> 7, s = (tid >> 5) & 3, cp = tid & 31;
            ull acc = 0;
            int j0 = s * 64;
            #pragma unroll 8
            for (int j = 0; j < 64; ++j)
                acc = fma2(((const ull*)(s_w2t + (j0 + j) * W2PAD))[cp],
                           s_h2[r * 256 + j0 + j], acc);
            s_red[tid] = acc;
        }
        __syncthreads();
        if (tid < 64) {
            int r = tid >> 5, cp = tid & 31;
            ull a = add2(add2(s_red[r * 128 + cp],      s_red[r * 128 + 32 + cp]),
                         add2(s_red[r * 128 + 64 + cp], s_red[r * 128 + 96 + cp]));
            float x0, x1; upk2(a, x0, x1);
            float a0, t; upk2(s_att2[r * 64 + 2 * cp], a0, t);
            float a1;    upk2(s_att2[r * 64 + 2 * cp + 1], a1, t);
            int row = row0 + r;
            if (row < Nq) {
                float2 o;
                o.x = a0 + x0 + lin2_b[2 * cp];
                o.y = a1 + x1 + lin2_b[2 * cp + 1];
                *(float2*)(g_x + row * 64 + 2 * cp) = o;
                ps0 += o.x; pq0 += o.x * o.x;
                ps1 += o.y; pq1 += o.y * o.y;
            }
        }
    }
    if (tid < 64) {
        int cp = tid & 31;
        atomicAdd(&g_sum1[2 * cp],     (double)ps0);
        atomicAdd(&g_sq1 [2 * cp],     (double)pq0);
        atomicAdd(&g_sum1[2 * cp + 1], (double)ps1);
        atomicAdd(&g_sq1 [2 * cp + 1], (double)pq1);
    }
}

__global__ void finalize1_kernel() {
    int t = threadIdx.x;
    if (t < Cdim) {
        double m = g_sum1[t] / (double)Nq;
        double v = g_sq1[t] / (double)Nq - m * m;
        if (v < 0) v = 0;
        g_mu1[t] = (float)m;
        g_rs1[t] = (float)(1.0 / sqrt(v + 1e-5));
    }
}

__global__ void finalize2_kernel() {
    int t = threadIdx.x;
    if (t < OUTd) {
        double m = g_sum2[t] / (double)Nq;
        double v = g_sq2[t] / (double)Nq - m * m;
        if (v < 0) v = 0;
        g_mu2[t] = (float)m;
        g_rs2[t] = (float)(1.0 / sqrt(v + 1e-5));
    }
}

// ============ BN1 + output linear (+fused BN2 stats) ============
__global__ __launch_bounds__(256) void proj_kernel(
    const float* __restrict__ outl_w, const float* __restrict__ outl_b,
    const float* __restrict__ norm_g, const float* __restrict__ norm_b)
{
    __shared__ float s_wt[64 * 65];
    __shared__ float s_x[16 * 64];
    __shared__ float s_ps[64], s_pq[64];
    int tid = threadIdx.x;

    if (tid < 64) { s_ps[tid] = 0.f; s_pq[tid] = 0.f; }
    for (int i = tid; i < 64 * 64; i += 256) {
        int o = i >> 6, c = i & 63;
        s_wt[c * 65 + o] = outl_w[i];
    }
    int base = blockIdx.x * 16 * 64;
    for (int i = tid; i < 16 * 64; i += 256) {
        int c = i & 63;
        s_x[i] = (g_x[base + i] - g_mu1[c]) * g_rs1[c] * norm_g[c] + norm_b[c];
    }
    __syncthreads();

    int o = tid & 63;
    float zs = 0.f, zq = 0.f;
    for (int rr = 0; rr < 4; ++rr) {
        int r = (tid >> 6) + rr * 4;
        const float* x = s_x + r * 64;
        float acc = outl_b[o];
        #pragma unroll
        for (int c = 0; c < 64; ++c) acc = fmaf(s_wt[c * 65 + o], x[c], acc);
        g_z[base + r * 64 + o] = acc;
        zs += acc; zq += acc * acc;
    }
    atomicAdd(&s_ps[o], zs);
    atomicAdd(&s_pq[o], zq);
    __syncthreads();
    if (tid < 64) {
        atomicAdd(&g_sum2[tid], (double)s_ps[tid]);
        atomicAdd(&g_sq2[tid],  (double)s_pq[tid]);
    }
}

__global__ void final_kernel(float* __restrict__ out,
                             const float* __restrict__ obn_g,
                             const float* __restrict__ obn_b)
{
    int i = blockIdx.x * 256 + threadIdx.x;
    if (i < Nq * OUTd) {
        int o = i & 63;
        float v = (g_z[i] - g_mu2[o]) * g_rs2[o] * obn_g[o] + obn_b[o];
        out[i] = fmaxf(v, 0.f);
    }
}

extern "C" void kernel_launch(void* const* d_in, const int* in_sizes, int n_in,
                              void* d_out, int out_size) {
    const float* vf     = (const float*)d_in[0];
    const float* vc     = (const float*)d_in[1];
    const float* qcoord = (const float*)d_in[2];
    const int*   kidx   = (const int*)  d_in[3];
    const float* q_w    = (const float*)d_in[4];
    const float* q_b    = (const float*)d_in[5];
    const float* kpos_w = (const float*)d_in[6];
    const float* kpos_b = (const float*)d_in[7];
    const float* in_w   = (const float*)d_in[8];
    const float* in_b   = (const float*)d_in[9];
    const float* out_w  = (const float*)d_in[10];
    const float* out_b  = (const float*)d_in[11];
    const float* lin1_w = (const float*)d_in[12];
    const float* lin1_b = (const float*)d_in[13];
    const float* lin2_w = (const float*)d_in[14];
    const float* lin2_b = (const float*)d_in[15];
    const float* norm_g = (const float*)d_in[16];
    const float* norm_b = (const float*)d_in[17];
    const float* outl_w = (const float*)d_in[18];
    const float* outl_b = (const float*)d_in[19];
    const float* obn_g  = (const float*)d_in[20];
    const float* obn_b  = (const float*)d_in[21];
    float* out = (float*)d_out;

    cudaFuncSetAttribute(attn_kernel, cudaFuncAttributeMaxDynamicSharedMemorySize, SMEM_ATTN);
    cudaFuncSetAttribute(ffn_kernel,  cudaFuncAttributeMaxDynamicSharedMemorySize, SMEM_FFN);

    zero_stats<<<1, 64>>>();
    qproj_kernel<<<(Nq + QRPB - 1) / QRPB, 256>>>(qcoord, q_w, q_b, in_w, in_b);
    attn_kernel<<<Nq / NQB, 192, SMEM_ATTN>>>(vf, vc, qcoord, kidx,
                                              kpos_w, kpos_b, in_w, in_b);
    ffn_kernel<<<(Nq + FRPB - 1) / FRPB, 256, SMEM_FFN>>>(out_w, out_b,
                                                          lin1_w, lin1_b, lin2_w, lin2_b);
    finalize1_kernel<<<1, 64>>>();
    proj_kernel<<<Nq / 16, 256>>>(outl_w, outl_b, norm_g, norm_b);
    finalize2_kernel<<<1, 64>>>();
    final_kernel<<<(Nq * OUTd + 255) / 256, 256>>>(out, obn_g, obn_b);
}

// round 7
// speedup vs baseline: 6.1665x; 1.7868x over previous
#include <cuda_runtime.h>
#include <math.h>

#define Nq   20000
#define KK   48
#define PADK 68
#define PADN 136

// ---- scratch ----
__device__ float  g_q[Nq * 64];
__device__ float  g_ctx[Nq * 64];
__device__ float  g_att[Nq * 64];
__device__ float  g_hid[Nq * 256];
__device__ float  g_x[Nq * 64];
__device__ float  g_z[Nq * 64];
__device__ double g_sum1[64], g_sq1[64];
__device__ double g_sum2[64], g_sq2[64];
__device__ float  g_mu1[64], g_rs1[64];
__device__ float  g_mu2[64], g_rs2[64];

__device__ __forceinline__ unsigned f2tf32(float x) {
    unsigned r; asm("cvt.rna.tf32.f32 %0, %1;" : "=r"(r) : "f"(x)); return r;
}
__device__ __forceinline__ void mma_tf32(float& d0, float& d1, float& d2, float& d3,
                                         unsigned a0, unsigned a1, unsigned a2, unsigned a3,
                                         unsigned b0, unsigned b1) {
    asm volatile("mma.sync.aligned.m16n8k8.row.col.f32.tf32.tf32.f32 "
                 "{%0,%1,%2,%3}, {%4,%5,%6,%7}, {%8,%9}, {%0,%1,%2,%3};"
                 : "+f"(d0), "+f"(d1), "+f"(d2), "+f"(d3)
                 : "r"(a0), "r"(a1), "r"(a2), "r"(a3), "r"(b0), "r"(b1));
}

__global__ void zero_stats() {
    int t = threadIdx.x;
    if (t < 64) { g_sum1[t] = 0.0; g_sq1[t] = 0.0; g_sum2[t] = 0.0; g_sq2[t] = 0.0; }
}

// ============================================================================
// qproj: g_q = (Wq @ relu(q_w qc + q_b) + bq) / 4        [Nq,64] x [64,64]
// ============================================================================
#define SM_Q ((64 * 72 + 128 * PADK) * 4)
__global__ __launch_bounds__(256) void qproj_mma(
    const float* __restrict__ qc, const float* __restrict__ q_w, const float* __restrict__ q_b,
    const float* __restrict__ in_w, const float* __restrict__ in_b)
{
    extern __shared__ unsigned sm[];
    unsigned* s_W = sm;             // [64][72]  (Wq^T)
    unsigned* s_A = sm + 64 * 72;   // [128][68]
    const int tid = threadIdx.x, lane = tid & 31, w = tid >> 5;
    const int g = lane >> 2, tig = lane & 3, mr = w * 16;
    const int rows0 = blockIdx.x * 128;

    for (int i = tid; i < 4096; i += 256) {
        int n = i >> 6, k = i & 63;
        s_W[k * 72 + n] = f2tf32(in_w[n * 64 + k]);
    }
    {
        const int c = tid & 63;
        const float w0 = q_w[c*3], w1 = q_w[c*3+1], w2 = q_w[c*3+2], b = q_b[c];
        for (int i = tid; i < 128 * 64; i += 256) {
            int r = i >> 6, row = rows0 + r;
            float v = 0.f;
            if (row < Nq)
                v = fmaxf(b + w0*qc[row*3] + w1*qc[row*3+1] + w2*qc[row*3+2], 0.f);
            s_A[r * PADK + c] = f2tf32(v);
        }
    }
    __syncthreads();

    float acc[8][4] = {};
    #pragma unroll
    for (int ks = 0; ks < 8; ++ks) {
        int k0 = ks * 8;
        unsigned a0 = s_A[(mr+g)*PADK + k0 + tig];
        unsigned a1 = s_A[(mr+g+8)*PADK + k0 + tig];
        unsigned a2 = s_A[(mr+g)*PADK + k0 + tig + 4];
        unsigned a3 = s_A[(mr+g+8)*PADK + k0 + tig + 4];
        #pragma unroll
        for (int nt = 0; nt < 8; ++nt) {
            unsigned b0 = s_W[(k0+tig)*72 + nt*8 + g];
            unsigned b1 = s_W[(k0+tig+4)*72 + nt*8 + g];
            mma_tf32(acc[nt][0], acc[nt][1], acc[nt][2], acc[nt][3], a0, a1, a2, a3, b0, b1);
        }
    }
    #pragma unroll
    for (int nt = 0; nt < 8; ++nt) {
        int col = nt*8 + 2*tig;
        float b0 = in_b[col], b1 = in_b[col+1];
        int r0 = rows0 + mr + g, r1 = r0 + 8;
        if (r0 < Nq) { float2 o = {(acc[nt][0]+b0)*0.25f, (acc[nt][1]+b1)*0.25f};
                       *(float2*)(g_q + r0*64 + col) = o; }
        if (r1 < Nq) { float2 o = {(acc[nt][2]+b0)*0.25f, (acc[nt][3]+b1)*0.25f};
                       *(float2*)(g_q + r1*64 + col) = o; }
    }
}

// ============================================================================
// attention kernel: 4 queries/block, 384 threads, tf32 MMA K/V GEMM
// ============================================================================
#define SMEM_ATTN ((192*PADK + 64*PADN + 256 + 768 + 576 + 192) * 4)
__global__ __launch_bounds__(384) void attn_kernel(
    const float* __restrict__ vf,     const float* __restrict__ vc,
    const float* __restrict__ qc,     const int*   __restrict__ kidx,
    const float* __restrict__ kpos_w, const float* __restrict__ kpos_b,
    const float* __restrict__ in_w,   const float* __restrict__ in_b)
{
    extern __shared__ char smem[];
    float* s_kf  = (float*)smem;                 // 192*68  (alias vp)
    float* s_B   = s_kf + 192 * PADK;            // 64*136
    float* s_q   = s_B + 64 * PADN;              // 256
    float* s_sc  = s_q + 256;                    // 4*4*48
    float* s_rel = s_sc + 768;                   // 192*3
    int*   s_idx = (int*)(s_rel + 576);          // 192

    const int tid  = threadIdx.x;
    const int lane = tid & 31;
    const int w    = tid >> 5;            // 0..11
    const int n0   = blockIdx.x * 4;

    for (int i = tid; i < 8192; i += 384) {
        int n = i >> 6, k = i & 63;
        ((unsigned*)s_B)[k * PADN + n] = f2tf32(in_w[4096 + i]);
    }
    if (tid < 192) {
        int q = tid / KK, kk = tid - q * KK;
        int n = n0 + q;
        int idx = kidx[n * KK + kk];
        s_idx[tid] = idx;
        int safe = idx < 0 ? 0 : idx;
        s_rel[tid*3+0] = vc[safe*3+0] - qc[n*3+0];
        s_rel[tid*3+1] = vc[safe*3+1] - qc[n*3+1];
        s_rel[tid*3+2] = vc[safe*3+2] - qc[n*3+2];
    }
    if (tid < 256) s_q[tid] = g_q[(n0 + (tid >> 6)) * 64 + (tid & 63)];
    __syncthreads();

    {
        const int c = tid & 63;
        const float kw0 = kpos_w[c*3], kw1 = kpos_w[c*3+1], kw2 = kpos_w[c*3+2];
        const float kb  = kpos_b[c];
        for (int e = tid; e < 192 * 64; e += 384) {
            int kg = e >> 6;
            int idx = s_idx[kg]; if (idx < 0) idx = 0;
            float f = vf[idx * 64 + c];
            float p = kb + kw0*s_rel[kg*3] + kw1*s_rel[kg*3+1] + kw2*s_rel[kg*3+2];
            ((unsigned*)s_kf)[kg * PADK + c] = f2tf32(f + fmaxf(p, 0.f));
        }
    }
    __syncthreads();

    const int g   = lane >> 2;
    const int tig = lane & 3;
    const int mr  = w * 16;

    float acc[16][4];
    #pragma unroll
    for (int nt = 0; nt < 16; ++nt)
        #pragma unroll
        for (int j = 0; j < 4; ++j) acc[nt][j] = 0.f;

    {
        const unsigned* kfu = (const unsigned*)s_kf;
        const unsigned* Bu  = (const unsigned*)s_B;
        const unsigned* arow0 = kfu + (mr + g) * PADK + tig;
        const unsigned* arow1 = kfu + (mr + g + 8) * PADK + tig;
        #pragma unroll
        for (int ks = 0; ks < 8; ++ks) {
            const int k0 = ks * 8;
            unsigned a0 = arow0[k0], a2 = arow0[k0 + 4];
            unsigned a1 = arow1[k0], a3 = arow1[k0 + 4];
            const unsigned* b0p = Bu + (k0 + tig) * PADN + g;
            const unsigned* b1p = Bu + (k0 + tig + 4) * PADN + g;
            #pragma unroll
            for (int nt = 0; nt < 16; ++nt) {
                unsigned b0 = b0p[nt * 8];
                unsigned b1 = b1p[nt * 8];
                mma_tf32(acc[nt][0], acc[nt][1], acc[nt][2], acc[nt][3],
                         a0, a1, a2, a3, b0, b1);
            }
        }
    }
    #pragma unroll
    for (int nt = 0; nt < 8; ++nt) {
        int cc = 8 * nt + 2 * tig;
        float b0 = in_b[64 + cc], b1 = in_b[64 + cc + 1];
        acc[nt][0] += b0; acc[nt][1] += b1;
        acc[nt][2] += b0; acc[nt][3] += b1;
    }
    {
        const int qsel = w / 3;
        const int qb = qsel * 64;
        const int keyb = (w - qsel * 3) * 16 + g;
        #pragma unroll
        for (int h = 0; h < 4; ++h) {
            int nA = 2 * h, nB = 2 * h + 1;
            int cA = 8 * nA + 2 * tig, cB = 8 * nB + 2 * tig;
            float qA0 = s_q[qb + cA], qA1 = s_q[qb + cA + 1];
            float qB0 = s_q[qb + cB], qB1 = s_q[qb + cB + 1];
            float s0 = acc[nA][0]*qA0 + acc[nA][1]*qA1 + acc[nB][0]*qB0 + acc[nB][1]*qB1;
            float s1 = acc[nA][2]*qA0 + acc[nA][3]*qA1 + acc[nB][2]*qB0 + acc[nB][3]*qB1;
            s0 += __shfl_xor_sync(0xffffffffu, s0, 1);
            s0 += __shfl_xor_sync(0xffffffffu, s0, 2);
            s1 += __shfl_xor_sync(0xffffffffu, s1, 1);
            s1 += __shfl_xor_sync(0xffffffffu, s1, 2);
            if (tig == 0) {
                int rbase = qsel * 48 + keyb;
                s_sc[(qsel * 4 + h) * 48 + keyb]     = (s_idx[rbase]     < 0) ? -1e30f : s0;
                s_sc[(qsel * 4 + h) * 48 + keyb + 8] = (s_idx[rbase + 8] < 0) ? -1e30f : s1;
            }
        }
    }
    __syncthreads();

    {
        float* s_vp = s_kf;
        const int row0 = mr + g;
        #pragma unroll
        for (int nt = 8; nt < 16; ++nt) {
            int cc = 8 * (nt - 8) + 2 * tig;
            float b0 = in_b[128 + cc], b1 = in_b[128 + cc + 1];
            s_vp[row0 * PADK + cc]           = acc[nt][0] + b0;
            s_vp[row0 * PADK + cc + 1]       = acc[nt][1] + b1;
            s_vp[(row0 + 8) * PADK + cc]     = acc[nt][2] + b0;
            s_vp[(row0 + 8) * PADK + cc + 1] = acc[nt][3] + b1;
        }
    }
    for (int r = w; r < 16; r += 12) {
        float* sc = s_sc + r * 48;
        float v0 = sc[lane];
        float v1 = (lane < 16) ? sc[32 + lane] : -1e30f;
        float m = fmaxf(v0, v1);
        #pragma unroll
        for (int o = 16; o > 0; o >>= 1) m = fmaxf(m, __shfl_xor_sync(0xffffffffu, m, o));
        float e0 = __expf(v0 - m);
        float e1 = (lane < 16) ? __expf(v1 - m) : 0.f;
        float s = e0 + e1;
        #pragma unroll
        for (int o = 16; o > 0; o >>= 1) s += __shfl_xor_sync(0xffffffffu, s, o);
        float inv = 1.f / s;
        sc[lane] = e0 * inv;
        if (lane < 16) sc[32 + lane] = e1 * inv;
    }
    __syncthreads();

    if (tid < 256) {
        int q = tid >> 6, c = tid & 63, h = c >> 4;
        const float* a  = s_sc + (q * 4 + h) * 48;
        const float* vp = s_kf + (q * 48) * PADK + c;
        float acc2 = 0.f;
        #pragma unroll 8
        for (int kk = 0; kk < KK; ++kk) acc2 = fmaf(a[kk], vp[kk * PADK], acc2);
        g_ctx[(n0 + q) * 64 + c] = acc2;
    }
}

// ============================================================================
// ffn1: g_att = g_ctx @ out_w^T + out_b        [Nq,64] x [64,64]
// ============================================================================
#define SM_F1 ((64 * 72 + 128 * PADK) * 4)
__global__ __launch_bounds__(256) void ffn1_mma(
    const float* __restrict__ out_w, const float* __restrict__ out_b)
{
    extern __shared__ unsigned sm[];
    unsigned* s_W = sm;             // [64][72]
    unsigned* s_A = sm + 64 * 72;   // [128][68]
    const int tid = threadIdx.x, lane = tid & 31, w = tid >> 5;
    const int g = lane >> 2, tig = lane & 3, mr = w * 16;
    const int rows0 = blockIdx.x * 128;

    for (int i = tid; i < 4096; i += 256) {
        int n = i >> 6, k = i & 63;
        s_W[k * 72 + n] = f2tf32(out_w[n * 64 + k]);
    }
    for (int i = tid; i < 128 * 64; i += 256) {
        int r = i >> 6, c = i & 63, row = rows0 + r;
        s_A[r * PADK + c] = f2tf32(row < Nq ? g_ctx[row * 64 + c] : 0.f);
    }
    __syncthreads();

    float acc[8][4] = {};
    #pragma unroll
    for (int ks = 0; ks < 8; ++ks) {
        int k0 = ks * 8;
        unsigned a0 = s_A[(mr+g)*PADK + k0 + tig];
        unsigned a1 = s_A[(mr+g+8)*PADK + k0 + tig];
        unsigned a2 = s_A[(mr+g)*PADK + k0 + tig + 4];
        unsigned a3 = s_A[(mr+g+8)*PADK + k0 + tig + 4];
        #pragma unroll
        for (int nt = 0; nt < 8; ++nt) {
            unsigned b0 = s_W[(k0+tig)*72 + nt*8 + g];
            unsigned b1 = s_W[(k0+tig+4)*72 + nt*8 + g];
            mma_tf32(acc[nt][0], acc[nt][1], acc[nt][2], acc[nt][3], a0, a1, a2, a3, b0, b1);
        }
    }
    #pragma unroll
    for (int nt = 0; nt < 8; ++nt) {
        int col = nt*8 + 2*tig;
        float b0 = out_b[col], b1 = out_b[col+1];
        int r0 = rows0 + mr + g, r1 = r0 + 8;
        if (r0 < Nq) { float2 o = {acc[nt][0]+b0, acc[nt][1]+b1};
                       *(float2*)(g_att + r0*64 + col) = o; }
        if (r1 < Nq) { float2 o = {acc[nt][2]+b0, acc[nt][3]+b1};
                       *(float2*)(g_att + r1*64 + col) = o; }
    }
}

// ============================================================================
// ffn2: g_hid = relu(g_att @ lin1_w^T + lin1_b)     [Nq,64] x [64,256]
// ============================================================================
#define SM_F2 ((64 * 264 + 64 * PADK) * 4)
__global__ __launch_bounds__(256) void ffn2_mma(
    const float* __restrict__ lin1_w, const float* __restrict__ lin1_b)
{
    extern __shared__ unsigned sm[];
    unsigned* s_W = sm;              // [64][264]
    unsigned* s_A = sm + 64 * 264;   // [64][68]
    const int tid = threadIdx.x, lane = tid & 31, w = tid >> 5;
    const int g = lane >> 2, tig = lane & 3;
    const int mr = (w & 3) * 16, nbase = (w >> 2) * 128;
    const int rows0 = blockIdx.x * 64;

    for (int i = tid; i < 16384; i += 256) {
        int n = i >> 6, k = i & 63;
        s_W[k * 264 + n] = f2tf32(lin1_w[n * 64 + k]);
    }
    for (int i = tid; i < 64 * 64; i += 256) {
        int r = i >> 6, c = i & 63, row = rows0 + r;
        s_A[r * PADK + c] = f2tf32(row < Nq ? g_att[row * 64 + c] : 0.f);
    }
    __syncthreads();

    float acc[16][4];
    #pragma unroll
    for (int nt = 0; nt < 16; ++nt)
        #pragma unroll
        for (int j = 0; j < 4; ++j) acc[nt][j] = 0.f;

    #pragma unroll
    for (int ks = 0; ks < 8; ++ks) {
        int k0 = ks * 8;
        unsigned a0 = s_A[(mr+g)*PADK + k0 + tig];
        unsigned a1 = s_A[(mr+g+8)*PADK + k0 + tig];
        unsigned a2 = s_A[(mr+g)*PADK + k0 + tig + 4];
        unsigned a3 = s_A[(mr+g+8)*PADK + k0 + tig + 4];
        #pragma unroll
        for (int nt = 0; nt < 16; ++nt) {
            unsigned b0 = s_W[(k0+tig)*264 + nbase + nt*8 + g];
            unsigned b1 = s_W[(k0+tig+4)*264 + nbase + nt*8 + g];
            mma_tf32(acc[nt][0], acc[nt][1], acc[nt][2], acc[nt][3], a0, a1, a2, a3, b0, b1);
        }
    }
    #pragma unroll
    for (int nt = 0; nt < 16; ++nt) {
        int col = nbase + nt*8 + 2*tig;
        float b0 = lin1_b[col], b1 = lin1_b[col+1];
        int r0 = rows0 + mr + g, r1 = r0 + 8;
        if (r0 < Nq) { float2 o = {fmaxf(acc[nt][0]+b0, 0.f), fmaxf(acc[nt][1]+b1, 0.f)};
                       *(float2*)(g_hid + r0*256 + col) = o; }
        if (r1 < Nq) { float2 o = {fmaxf(acc[nt][2]+b0, 0.f), fmaxf(acc[nt][3]+b1, 0.f)};
                       *(float2*)(g_hid + r1*256 + col) = o; }
    }
}

// ============================================================================
// ffn3: g_x = g_att + g_hid @ lin2_w^T + lin2_b, accumulate BN1 stats
// ============================================================================
#define SM_F3 ((256 * 72 + 128 * PADK + 128) * 4)
__global__ __launch_bounds__(256) void ffn3_mma(
    const float* __restrict__ lin2_w, const float* __restrict__ lin2_b)
{
    extern __shared__ unsigned sm[];
    unsigned* s_W = sm;               // [256][72]
    unsigned* s_A = sm + 256 * 72;    // [128][68]
    float* s_ps = (float*)(s_A + 128 * PADK);   // [64]
    float* s_pq = s_ps + 64;                    // [64]
    const int tid = threadIdx.x, lane = tid & 31, w = tid >> 5;
    const int g = lane >> 2, tig = lane & 3, mr = w * 16;
    const int rows0 = blockIdx.x * 128;

    if (tid < 64) { s_ps[tid] = 0.f; s_pq[tid] = 0.f; }
    // lin2_w is [64 out][256 in]: k = inner (0..255), n = output (0..63)
    for (int i = tid; i < 16384; i += 256) {
        int k = i >> 6, n = i & 63;
        s_W[k * 72 + n] = f2tf32(lin2_w[n * 256 + k]);
    }

    float acc[8][4] = {};
    for (int kc = 0; kc < 4; ++kc) {
        __syncthreads();
        for (int i = tid; i < 128 * 64; i += 256) {
            int r = i >> 6, c = i & 63, row = rows0 + r;
            s_A[r * PADK + c] = f2tf32(row < Nq ? g_hid[row * 256 + kc * 64 + c] : 0.f);
        }
        __syncthreads();
        #pragma unroll
        for (int ks = 0; ks < 8; ++ks) {
            int k0 = ks * 8;
            unsigned a0 = s_A[(mr+g)*PADK + k0 + tig];
            unsigned a1 = s_A[(mr+g+8)*PADK + k0 + tig];
            unsigned a2 = s_A[(mr+g)*PADK + k0 + tig + 4];
            unsigned a3 = s_A[(mr+g+8)*PADK + k0 + tig + 4];
            int kw = kc * 64 + k0;
            #pragma unroll
            for (int nt = 0; nt < 8; ++nt) {
                unsigned b0 = s_W[(kw+tig)*72 + nt*8 + g];
                unsigned b1 = s_W[(kw+tig+4)*72 + nt*8 + g];
                mma_tf32(acc[nt][0], acc[nt][1], acc[nt][2], acc[nt][3], a0, a1, a2, a3, b0, b1);
            }
        }
    }

    #pragma unroll
    for (int nt = 0; nt < 8; ++nt) {
        int col = nt*8 + 2*tig;
        float b0 = lin2_b[col], b1 = lin2_b[col+1];
        int r0 = rows0 + mr + g, r1 = r0 + 8;
        bool v0 = r0 < Nq, v1 = r1 < Nq;
        float2 a0r = v0 ? *(const float2*)(g_att + r0*64 + col) : make_float2(0.f, 0.f);
        float2 a1r = v1 ? *(const float2*)(g_att + r1*64 + col) : make_float2(0.f, 0.f);
        float x00 = acc[nt][0] + b0 + a0r.x, x01 = acc[nt][1] + b1 + a0r.y;
        float x10 = acc[nt][2] + b0 + a1r.x, x11 = acc[nt][3] + b1 + a1r.y;
        if (v0) { float2 o = {x00, x01}; *(float2*)(g_x + r0*64 + col) = o; }
        if (v1) { float2 o = {x10, x11}; *(float2*)(g_x + r1*64 + col) = o; }
        float m00 = v0 ? x00 : 0.f, m01 = v0 ? x01 : 0.f;
        float m10 = v1 ? x10 : 0.f, m11 = v1 ? x11 : 0.f;
        float se = m00 + m10,                 so = m01 + m11;
        float sq = m00*m00 + m10*m10,         qo = m01*m01 + m11*m11;
        #pragma unroll
        for (int o = 16; o >= 4; o >>= 1) {
            se += __shfl_down_sync(0xffffffffu, se, o);
            so += __shfl_down_sync(0xffffffffu, so, o);
            sq += __shfl_down_sync(0xffffffffu, sq, o);
            qo += __shfl_down_sync(0xffffffffu, qo, o);
        }
        if (lane < 4) {
            atomicAdd(&s_ps[col], se);  atomicAdd(&s_pq[col], sq);
            atomicAdd(&s_ps[col+1], so); atomicAdd(&s_pq[col+1], qo);
        }
    }
    __syncthreads();
    if (tid < 64) {
        atomicAdd(&g_sum1[tid], (double)s_ps[tid]);
        atomicAdd(&g_sq1[tid],  (double)s_pq[tid]);
    }
}

__global__ void finalize1_kernel() {
    int t = threadIdx.x;
    if (t < 64) {
        double m = g_sum1[t] / (double)Nq;
        double v = g_sq1[t] / (double)Nq - m * m;
        if (v < 0) v = 0;
        g_mu1[t] = (float)m;
        g_rs1[t] = (float)(1.0 / sqrt(v + 1e-5));
    }
}

__global__ void finalize2_kernel() {
    int t = threadIdx.x;
    if (t < 64) {
        double m = g_sum2[t] / (double)Nq;
        double v = g_sq2[t] / (double)Nq - m * m;
        if (v < 0) v = 0;
        g_mu2[t] = (float)m;
        g_rs2[t] = (float)(1.0 / sqrt(v + 1e-5));
    }
}

// ============================================================================
// proj: g_z = BN1(g_x) @ outl_w^T + outl_b, accumulate BN2 stats
// ============================================================================
#define SM_P ((64 * 72 + 128 * PADK + 128) * 4)
__global__ __launch_bounds__(256) void proj_mma(
    const float* __restrict__ outl_w, const float* __restrict__ outl_b,
    const float* __restrict__ norm_g, const float* __restrict__ norm_b)
{
    extern __shared__ unsigned sm[];
    unsigned* s_W = sm;             // [64][72]
    unsigned* s_A = sm + 64 * 72;   // [128][68]
    float* s_ps = (float*)(s_A + 128 * PADK);
    float* s_pq = s_ps + 64;
    const int tid = threadIdx.x, lane = tid & 31, w = tid >> 5;
    const int g = lane >> 2, tig = lane & 3, mr = w * 16;
    const int rows0 = blockIdx.x * 128;

    if (tid < 64) { s_ps[tid] = 0.f; s_pq[tid] = 0.f; }
    for (int i = tid; i < 4096; i += 256) {
        int n = i >> 6, k = i & 63;
        s_W[k * 72 + n] = f2tf32(outl_w[n * 64 + k]);
    }
    {
        const int c = tid & 63;
        const float mu = g_mu1[c], rs = g_rs1[c], ga = norm_g[c], be = norm_b[c];
        for (int i = tid; i < 128 * 64; i += 256) {
            int r = i >> 6, row = rows0 + r;
            float v = 0.f;
            if (row < Nq) v = (g_x[row * 64 + c] - mu) * rs * ga + be;
            s_A[r * PADK + c] = f2tf32(v);
        }
    }
    __syncthreads();

    float acc[8][4] = {};
    #pragma unroll
    for (int ks = 0; ks < 8; ++ks) {
        int k0 = ks * 8;
        unsigned a0 = s_A[(mr+g)*PADK + k0 + tig];
        unsigned a1 = s_A[(mr+g+8)*PADK + k0 + tig];
        unsigned a2 = s_A[(mr+g)*PADK + k0 + tig + 4];
        unsigned a3 = s_A[(mr+g+8)*PADK + k0 + tig + 4];
        #pragma unroll
        for (int nt = 0; nt < 8; ++nt) {
            unsigned b0 = s_W[(k0+tig)*72 + nt*8 + g];
            unsigned b1 = s_W[(k0+tig+4)*72 + nt*8 + g];
            mma_tf32(acc[nt][0], acc[nt][1], acc[nt][2], acc[nt][3], a0, a1, a2, a3, b0, b1);
        }
    }
    #pragma unroll
    for (int nt = 0; nt < 8; ++nt) {
        int col = nt*8 + 2*tig;
        float b0 = outl_b[col], b1 = outl_b[col+1];
        int r0 = rows0 + mr + g, r1 = r0 + 8;
        bool v0 = r0 < Nq, v1 = r1 < Nq;
        float x00 = acc[nt][0] + b0, x01 = acc[nt][1] + b1;
        float x10 = acc[nt][2] + b0, x11 = acc[nt][3] + b1;
        if (v0) { float2 o = {x00, x01}; *(float2*)(g_z + r0*64 + col) = o; }
        if (v1) { float2 o = {x10, x11}; *(float2*)(g_z + r1*64 + col) = o; }
        float m00 = v0 ? x00 : 0.f, m01 = v0 ? x01 : 0.f;
        float m10 = v1 ? x10 : 0.f, m11 = v1 ? x11 : 0.f;
        float se = m00 + m10,                 so = m01 + m11;
        float sq = m00*m00 + m10*m10,         qo = m01*m01 + m11*m11;
        #pragma unroll
        for (int o = 16; o >= 4; o >>= 1) {
            se += __shfl_down_sync(0xffffffffu, se, o);
            so += __shfl_down_sync(0xffffffffu, so, o);
            sq += __shfl_down_sync(0xffffffffu, sq, o);
            qo += __shfl_down_sync(0xffffffffu, qo, o);
        }
        if (lane < 4) {
            atomicAdd(&s_ps[col], se);  atomicAdd(&s_pq[col], sq);
            atomicAdd(&s_ps[col+1], so); atomicAdd(&s_pq[col+1], qo);
        }
    }
    __syncthreads();
    if (tid < 64) {
        atomicAdd(&g_sum2[tid], (double)s_ps[tid]);
        atomicAdd(&g_sq2[tid],  (double)s_pq[tid]);
    }
}

__global__ void final_kernel(float* __restrict__ out,
                             const float* __restrict__ obn_g,
                             const float* __restrict__ obn_b)
{
    int i = blockIdx.x * 256 + threadIdx.x;
    if (i < Nq * 64) {
        int o = i & 63;
        float v = (g_z[i] - g_mu2[o]) * g_rs2[o] * obn_g[o] + obn_b[o];
        out[i] = fmaxf(v, 0.f);
    }
}

extern "C" void kernel_launch(void* const* d_in, const int* in_sizes, int n_in,
                              void* d_out, int out_size) {
    const float* vf     = (const float*)d_in[0];
    const float* vc     = (const float*)d_in[1];
    const float* qcoord = (const float*)d_in[2];
    const int*   kidx   = (const int*)  d_in[3];
    const float* q_w    = (const float*)d_in[4];
    const float* q_b    = (const float*)d_in[5];
    const float* kpos_w = (const float*)d_in[6];
    const float* kpos_b = (const float*)d_in[7];
    const float* in_w   = (const float*)d_in[8];
    const float* in_b   = (const float*)d_in[9];
    const float* out_w  = (const float*)d_in[10];
    const float* out_b  = (const float*)d_in[11];
    const float* lin1_w = (const float*)d_in[12];
    const float* lin1_b = (const float*)d_in[13];
    const float* lin2_w = (const float*)d_in[14];
    const float* lin2_b = (const float*)d_in[15];
    const float* norm_g = (const float*)d_in[16];
    const float* norm_b = (const float*)d_in[17];
    const float* outl_w = (const float*)d_in[18];
    const float* outl_b = (const float*)d_in[19];
    const float* obn_g  = (const float*)d_in[20];
    const float* obn_b  = (const float*)d_in[21];
    float* out = (float*)d_out;

    cudaFuncSetAttribute(attn_kernel, cudaFuncAttributeMaxDynamicSharedMemorySize, SMEM_ATTN);
    cudaFuncSetAttribute(qproj_mma,   cudaFuncAttributeMaxDynamicSharedMemorySize, SM_Q);
    cudaFuncSetAttribute(ffn1_mma,    cudaFuncAttributeMaxDynamicSharedMemorySize, SM_F1);
    cudaFuncSetAttribute(ffn2_mma,    cudaFuncAttributeMaxDynamicSharedMemorySize, SM_F2);
    cudaFuncSetAttribute(ffn3_mma,    cudaFuncAttributeMaxDynamicSharedMemorySize, SM_F3);
    cudaFuncSetAttribute(proj_mma,    cudaFuncAttributeMaxDynamicSharedMemorySize, SM_P);

    const int RB = (Nq + 127) / 128;   // 157

    zero_stats<<<1, 64>>>();
    qproj_mma<<<RB, 256, SM_Q>>>(qcoord, q_w, q_b, in_w, in_b);
    attn_kernel<<<Nq / 4, 384, SMEM_ATTN>>>(vf, vc, qcoord, kidx,
                                            kpos_w, kpos_b, in_w, in_b);
    ffn1_mma<<<RB, 256, SM_F1>>>(out_w, out_b);
    ffn2_mma<<<(Nq + 63) / 64, 256, SM_F2>>>(lin1_w, lin1_b);
    ffn3_mma<<<RB, 256, SM_F3>>>(lin2_w, lin2_b);
    finalize1_kernel<<<1, 64>>>();
    proj_mma<<<RB, 256, SM_P>>>(outl_w, outl_b, norm_g, norm_b);
    finalize2_kernel<<<1, 64>>>();
    final_kernel<<<(Nq * 64 + 255) / 256, 256>>>(out, obn_g, obn_b);
}